// round 11
// baseline (speedup 1.0000x reference)
#include <cuda_runtime.h>
#include <math.h>

typedef unsigned long long ull;

// ---------------- problem constants ----------------
#define BB   16
#define C1   64
#define T1   4096
#define CO   32
#define T2   2048
#define T3   2019
#define HH   64
#define NST  64
#define NL   8
#define DOUT 640
#define EPSF 1e-5f

// ---------------- f32x2 packed helpers ----------------
__device__ __forceinline__ ull pk2(float a, float b) {
    ull r; asm("mov.b64 %0, {%1, %2};" : "=l"(r) : "f"(a), "f"(b)); return r;
}
__device__ __forceinline__ void upk2(ull v, float& a, float& b) {
    asm("mov.b64 {%0, %1}, %2;" : "=f"(a), "=f"(b) : "l"(v));
}
__device__ __forceinline__ ull ffma2(ull a, ull b, ull c) {
    ull r; asm("fma.rn.f32x2 %0, %1, %2, %3;" : "=l"(r) : "l"(a), "l"(b), "l"(c)); return r;
}

// ---------------- scratch ----------------
__device__ float g_u1[BB*CO*T1];
__device__ float g_u2[BB*CO*T3];
__device__ float g_h [BB*HH*T3];
__device__ float g_y [BB*HH*T3];
__device__ float g_st1[BB*2];
__device__ float g_st2[BB*2];
__device__ float g_Wm [HH*CO];
__device__ float g_bv [HH];

// block-scan matrices per (lay,h)
__device__ float g_M [NL*HH*32*160];   // [lh][j 0..31][r 0..159]: rows 0..31 = T, 32..159 = V(pair-layout)
__device__ float g_Wc[NL*HH*128*32];   // [lh][k 0..127][i 0..31]
__device__ ull   g_A32[NL*HH*3*32];    // [lh][{ar,ai,-ai}][lane]

// ---------------- S4D block-scan matrix precompute ----------------
__global__ void k_s4c(const float* __restrict__ logdt, const float* __restrict__ logA,
                      const float* __restrict__ Aim,  const float* __restrict__ Cre,
                      const float* __restrict__ Cim,  const float* __restrict__ Dv) {
    __shared__ float apr[33][64], api[33][64];
    __shared__ float s_cr[64], s_ci[64], s_K[33];
    int h = blockIdx.x, lay = blockIdx.y, n = threadIdx.x;   // 64 threads
    int lh = lay*HH + h;
    if (h == 0 && lay == 0 && n < BB*2) { g_st1[n] = 0.f; g_st2[n] = 0.f; }
    int src = lh*NST + n;
    float dt  = expf(logdt[lh]);
    float Are = -expf(logA[src]);
    float Aii = Aim[src];
    float e = expf(Are * dt);
    float are = e * cosf(Aii * dt);
    float aim = e * sinf(Aii * dt);
    float nre = are - 1.f, nim = aim;
    float den = Are*Are + Aii*Aii;
    float qre = (nre*Are + nim*Aii) / den;
    float qim = (nim*Are - nre*Aii) / den;
    float cre = Cre[src], cim = Cim[src];
    float cr = 2.f*(cre*qre - cim*qim);
    float ci = 2.f*(cre*qim + cim*qre);
    s_cr[n] = cr; s_ci[n] = ci;
    float pr = 1.f, pi = 0.f;
    apr[0][n] = 1.f; api[0][n] = 0.f;
#pragma unroll
    for (int d = 1; d <= 32; d++) {
        float nr = pr*are - pi*aim;
        pi = pr*aim + pi*are; pr = nr;
        apr[d][n] = pr; api[d][n] = pi;
    }
    __syncthreads();
    if (n < 33) {
        float K = 0.f;
        for (int m = 0; m < 64; m++)
            K += s_cr[m]*apr[n][m] - s_ci[m]*api[n][m];
        s_K[n] = K;
    }
    __syncthreads();
    float Dh = Dv[lh];
    // M: [j][r]
    for (int idx = n; idx < 32*160; idx += 64) {
        int j = idx / 160, r = idx % 160;
        float v;
        if (r < 32) {
            int d = r - j;
            v = (d < 0) ? 0.f : (s_K[d] + (d == 0 ? Dh : 0.f));
        } else {
            int vr = r - 32;
            if (vr < 64) { int s = (vr >> 1) + ((vr & 1) << 5); v = apr[31 - j][s]; }
            else { int vv = vr - 64; int s = (vv >> 1) + ((vv & 1) << 5); v = api[31 - j][s]; }
        }
        g_M[lh*5120 + idx] = v;
    }
    // W: [k][i]; S rows: k<64 -> Sr_state k; k>=64 -> Si_state (k-64)
    for (int idx = n; idx < 128*32; idx += 64) {
        int k = idx >> 5, i = idx & 31;
        float w;
        if (k < 64) w = s_cr[k]*apr[i+1][k] - s_ci[k]*api[i+1][k];
        else { int s = k - 64; w = -(s_cr[s]*api[i+1][s] + s_ci[s]*apr[i+1][s]); }
        g_Wc[lh*4096 + idx] = w;
    }
    if (n < 32) {
        g_A32[lh*96 + n]      = pk2(apr[32][n],  apr[32][n+32]);
        g_A32[lh*96 + 32 + n] = pk2(api[32][n],  api[32][n+32]);
        g_A32[lh*96 + 64 + n] = pk2(-api[32][n], -api[32][n+32]);
    }
}

// ---------------- pw1 + GN1 stats ----------------
__global__ __launch_bounds__(256) void k_pw1(const float* __restrict__ x,
                                             const float* __restrict__ w,
                                             const float* __restrict__ bias) {
    __shared__ float xs[C1][128];
    __shared__ float wst[C1][34];
    __shared__ float rs[8], rss[8];
    int b = blockIdx.y, t0 = blockIdx.x * 128;
    int tid = threadIdx.x;
    for (int i = tid; i < C1*128; i += 256) {
        int c = i >> 7, tt = i & 127;
        xs[c][tt] = x[(b*C1 + c)*T1 + t0 + tt];
    }
    for (int i = tid; i < CO*C1; i += 256) {
        int o = i >> 6, c = i & 63;
        wst[c][o] = w[i];
    }
    __syncthreads();
    int tt = tid & 127, half = tid >> 7;
    int ob0 = half * 16;
    ull acc[8];
#pragma unroll
    for (int p = 0; p < 8; p++) acc[p] = pk2(bias[ob0 + 2*p], bias[ob0 + 2*p + 1]);
    for (int c = 0; c < C1; c++) {
        float xv = xs[c][tt];
        ull X = pk2(xv, xv);
#pragma unroll
        for (int p = 0; p < 8; p++) {
            ull wv = *(const ull*)&wst[c][ob0 + 2*p];
            acc[p] = ffma2(wv, X, acc[p]);
        }
    }
    float s = 0.f, ss = 0.f;
#pragma unroll
    for (int p = 0; p < 8; p++) {
        float a0, a1; upk2(acc[p], a0, a1);
        int o = ob0 + 2*p;
        g_u1[(b*CO + o)*T1 + t0 + tt]     = a0;
        g_u1[(b*CO + o + 1)*T1 + t0 + tt] = a1;
        s += a0 + a1; ss += a0*a0 + a1*a1;
    }
#pragma unroll
    for (int off = 16; off; off >>= 1) {
        s  += __shfl_xor_sync(0xffffffffu, s,  off);
        ss += __shfl_xor_sync(0xffffffffu, ss, off);
    }
    int wid = tid >> 5;
    if ((tid & 31) == 0) { rs[wid] = s; rss[wid] = ss; }
    __syncthreads();
    if (tid == 0) {
        float a = 0.f, q = 0.f;
        for (int i = 0; i < 8; i++) { a += rs[i]; q += rss[i]; }
        atomicAdd(&g_st1[b*2],     a);
        atomicAdd(&g_st1[b*2 + 1], q);
    }
}

// ---- GN1-apply + GLU(time) + SiLU + depthwise conv + GN2 stats ----
__global__ __launch_bounds__(256) void k_dwf(const float* __restrict__ w,
                                             const float* __restrict__ bias,
                                             const float* __restrict__ g1,
                                             const float* __restrict__ b1) {
    __shared__ float us[1024 + 36];
    __shared__ float wk[32];
    __shared__ float rs[8], rss[8];
    int t0 = blockIdx.x * 1024, c = blockIdx.y, b = blockIdx.z;
    int tid = threadIdx.x;
    if (tid < 32) wk[tid] = w[c*32 + tid];
    float n1 = (float)(CO * T1);
    float m1   = g_st1[b*2] / n1;
    float var1 = g_st1[b*2 + 1] / n1 - m1*m1;
    float rstd1 = rsqrtf(var1 + EPSF);
    float sc = rstd1 * g1[c], sh = b1[c] - m1 * sc;
    const float* base = g_u1 + (b*CO + c)*T1;
    for (int i = tid; i < 1060; i += 256) {
        int gi = t0 - 1 + i;
        float v = 0.f;
        if (gi >= 0 && gi < T2) {
            float ga = fmaf(base[gi],      sc, sh);
            float gb = fmaf(base[gi + T2], sc, sh);
            v = ga / (1.f + __expf(-gb));
            v = v / (1.f + __expf(-v));
        }
        us[i] = v;
    }
    __syncthreads();
    int tt = tid * 4;
    float uw[36];
#pragma unroll
    for (int q = 0; q < 9; q++) {
        float4 v = *(const float4*)&us[tt + q*4];
        uw[q*4+0] = v.x; uw[q*4+1] = v.y; uw[q*4+2] = v.z; uw[q*4+3] = v.w;
    }
    float bc = bias[c];
    float a0 = bc, a1 = bc, a2 = bc, a3 = bc;
#pragma unroll
    for (int k = 0; k < 32; k++) {
        float wv = wk[k];
        a0 = fmaf(wv, uw[k],     a0);
        a1 = fmaf(wv, uw[k + 1], a1);
        a2 = fmaf(wv, uw[k + 2], a2);
        a3 = fmaf(wv, uw[k + 3], a3);
    }
    float s = 0.f, ss = 0.f;
    float* dst = g_u2 + (b*CO + c)*T3 + t0 + tt;
    float av[4] = {a0, a1, a2, a3};
#pragma unroll
    for (int r = 0; r < 4; r++) {
        int t = t0 + tt + r;
        if (t < T3) { dst[r] = av[r]; s += av[r]; ss += av[r]*av[r]; }
    }
#pragma unroll
    for (int off = 16; off; off >>= 1) {
        s  += __shfl_xor_sync(0xffffffffu, s,  off);
        ss += __shfl_xor_sync(0xffffffffu, ss, off);
    }
    int wid = tid >> 5;
    if ((tid & 31) == 0) { rs[wid] = s; rss[wid] = ss; }
    __syncthreads();
    if (tid == 0) {
        float a = 0.f, q = 0.f;
        for (int i = 0; i < 8; i++) { a += rs[i]; q += rss[i]; }
        atomicAdd(&g_st2[b*2],     a);
        atomicAdd(&g_st2[b*2 + 1], q);
    }
}

// ---------------- fused (enc ∘ pw2) matrix ----------------
__global__ __launch_bounds__(256) void k_prep(const float* __restrict__ pw2w,
                                              const float* __restrict__ pw2b,
                                              const float* __restrict__ encw,
                                              const float* __restrict__ encb) {
    int i = blockIdx.x * 256 + threadIdx.x;
    if (i < HH*CO) {
        int d = i >> 5, cp = i & 31;
        float acc = 0.f;
#pragma unroll 8
        for (int c = 0; c < CO; c++)
            acc = fmaf(encw[c*HH + d], pw2w[c*CO + cp], acc);
        g_Wm[i] = acc;
    } else if (i < HH*CO + HH) {
        int d = i - HH*CO;
        float acc = encb[d];
#pragma unroll 8
        for (int c = 0; c < CO; c++)
            acc = fmaf(encw[c*HH + d], pw2b[c], acc);
        g_bv[d] = acc;
    }
}

// ---------------- GN2 apply + fused pw2∘enc -> h ----------------
__global__ __launch_bounds__(256) void k_enc(const float* __restrict__ g2,
                                             const float* __restrict__ b2) {
    __shared__ float un[CO][128];
    __shared__ float Wse[CO][66];
    int b = blockIdx.y, t0 = blockIdx.x * 128;
    int tid = threadIdx.x;
    float n = (float)(CO * T3);
    float m   = g_st2[b*2] / n;
    float var = g_st2[b*2 + 1] / n - m*m;
    float rstd = rsqrtf(var + EPSF);
    for (int i = tid; i < CO*128; i += 256) {
        int c = i >> 7, tt = i & 127;
        int t = t0 + tt;
        float v = (t < T3) ? g_u2[(b*CO + c)*T3 + t] : 0.f;
        un[c][tt] = (v - m) * rstd * g2[c] + b2[c];
    }
    for (int i = tid; i < HH*CO; i += 256) {
        int d = i >> 5, c = i & 31;
        Wse[c][d] = g_Wm[i];
    }
    __syncthreads();
    int tt = tid & 127, dg = tid >> 7;
    int d0 = dg * 32;
    ull acc[16];
#pragma unroll
    for (int p = 0; p < 16; p++) acc[p] = pk2(g_bv[d0 + 2*p], g_bv[d0 + 2*p + 1]);
    for (int c = 0; c < CO; c++) {
        float uv = un[c][tt];
        ull U = pk2(uv, uv);
#pragma unroll
        for (int p = 0; p < 16; p++) {
            ull wv = *(const ull*)&Wse[c][d0 + 2*p];
            acc[p] = ffma2(wv, U, acc[p]);
        }
    }
    int t = t0 + tt;
    if (t < T3) {
#pragma unroll
        for (int p = 0; p < 16; p++) {
            float a0, a1; upk2(acc[p], a0, a1);
            g_h[(b*HH + d0 + 2*p)*T3 + t]     = a0;
            g_h[(b*HH + d0 + 2*p + 1)*T3 + t] = a1;
        }
    }
}

// ---------------- block-scan S4D: GEMM-A + carry scan + GEMM-B + GELU ----------------
// smem float offsets
#define SM_M  0        // 5120: M [32 j][160 r]
#define SM_U  5120     // 2176: u [32 j][68 c]  (reused as Y1 [32 i][68 c])
#define SM_P  7296     // 8192: P [64 c][128 vr]
#define SM_S  15488    // 8704: S_T [128 k][68 c]
#define SM_W  24192    // 4096: W [128 k][32 i]
#define SM_TOT 28288   // floats -> 113152 bytes

__global__ __launch_bounds__(320, 2) void k_sc2(int lay) {
    extern __shared__ float sm[];
    int tid = threadIdx.x;
    int bh = blockIdx.x;
    int h = bh & 63;
    int lh = lay*HH + h;
    // loads
    const float* gm = g_M + lh*5120;
    for (int i = tid; i < 5120; i += 320) sm[SM_M + i] = gm[i];
    const float* gw = g_Wc + lh*4096;
    for (int i = tid; i < 4096; i += 320) sm[SM_W + i] = gw[i];
    const float* uin = g_h + bh*T3;
    for (int i = tid; i < 2048; i += 320) {
        int c = i >> 5, j = i & 31;
        sm[SM_U + j*68 + c] = (i < T3) ? uin[i] : 0.f;
    }
    __syncthreads();
    // ---- phase A GEMM: [160x32] @ [32x64] ----
    int r = tid % 160, cb = tid / 160;     // cb in {0,1}, 32 cols each
    int c0 = cb * 32;
    ull acc[16];
#pragma unroll
    for (int q = 0; q < 16; q++) acc[q] = 0ull;
#pragma unroll 4
    for (int k = 0; k < 32; k++) {
        float w = sm[SM_M + k*160 + r];
        ull wp = pk2(w, w);
        const ulonglong2* up = (const ulonglong2*)&sm[SM_U + k*68 + c0];
#pragma unroll
        for (int q4 = 0; q4 < 8; q4++) {
            ulonglong2 uv = up[q4];
            acc[q4*2]     = ffma2(wp, uv.x, acc[q4*2]);
            acc[q4*2 + 1] = ffma2(wp, uv.y, acc[q4*2 + 1]);
        }
    }
    __syncthreads();     // u fully consumed
    // epilogue: Y1 into u region; P into Psm
    if (r < 32) {
#pragma unroll
        for (int q = 0; q < 16; q++)
            *(ull*)&sm[SM_U + r*68 + c0 + 2*q] = acc[q];
    } else {
        int vr = r - 32;
#pragma unroll
        for (int q = 0; q < 16; q++) {
            float v0, v1; upk2(acc[q], v0, v1);
            sm[SM_P + (c0 + 2*q)*128 + vr]     = v0;
            sm[SM_P + (c0 + 2*q + 1)*128 + vr] = v1;
        }
    }
    __syncthreads();
    // ---- carry scan (warp 0): S[c+1] = a32 (.) S[c] + P[c] ----
    if (tid < 32) {
        int l = tid;
        const ull* ga = g_A32 + lh*96;
        ull A32r = ga[l], A32i = ga[32 + l], A32in = ga[64 + l];
        sm[SM_S + l*68] = 0.f; sm[SM_S + (l+32)*68] = 0.f;
        sm[SM_S + (64+l)*68] = 0.f; sm[SM_S + (96+l)*68] = 0.f;
        ull Sr = 0ull, Si = 0ull;
        ull Ppr = *(const ull*)&sm[SM_P + 2*l];
        ull Ppi = *(const ull*)&sm[SM_P + 64 + 2*l];
        for (int c = 0; c < 63; c++) {
            ull nPr = 0ull, nPi = 0ull;
            if (c < 62) {
                nPr = *(const ull*)&sm[SM_P + (c+1)*128 + 2*l];
                nPi = *(const ull*)&sm[SM_P + (c+1)*128 + 64 + 2*l];
            }
            ull t = ffma2(A32in, Si, Ppr);
            ull m = ffma2(A32i,  Sr, Ppi);
            Sr = ffma2(A32r, Sr, t);
            Si = ffma2(A32r, Si, m);
            float srl, srh, sil, sih;
            upk2(Sr, srl, srh); upk2(Si, sil, sih);
            sm[SM_S + l*68 + c + 1]      = srl;
            sm[SM_S + (l+32)*68 + c + 1] = srh;
            sm[SM_S + (64+l)*68 + c + 1] = sil;
            sm[SM_S + (96+l)*68 + c + 1] = sih;
            Ppr = nPr; Ppi = nPi;
        }
    }
    __syncthreads();
    // ---- phase B GEMM: Y2 = W[32x128] @ S[128x64]; y = gelu(Y1+Y2) ----
    if (tid < 128) {
        int i = tid >> 2, cb2 = tid & 3;
        int cc0 = cb2 * 16;
        ull acc2[8];
#pragma unroll
        for (int q = 0; q < 8; q++) acc2[q] = 0ull;
#pragma unroll 4
        for (int k = 0; k < 128; k++) {
            float w = sm[SM_W + k*32 + i];
            ull wp = pk2(w, w);
            const ulonglong2* sp = (const ulonglong2*)&sm[SM_S + k*68 + cc0];
#pragma unroll
            for (int q4 = 0; q4 < 4; q4++) {
                ulonglong2 sv = sp[q4];
                acc2[q4*2]     = ffma2(wp, sv.x, acc2[q4*2]);
                acc2[q4*2 + 1] = ffma2(wp, sv.y, acc2[q4*2 + 1]);
            }
        }
        float* yo = g_y + bh*T3;
#pragma unroll
        for (int q = 0; q < 8; q++) {
            float v0, v1; upk2(acc2[q], v0, v1);
            int c = cc0 + 2*q;
            float y0 = v0 + sm[SM_U + i*68 + c];
            float y1 = v1 + sm[SM_U + i*68 + c + 1];
            y0 = 0.5f * y0 * (1.f + erff(y0 * 0.70710678118f));
            y1 = 0.5f * y1 * (1.f + erff(y1 * 0.70710678118f));
            int t0 = c*32 + i;
            if (t0 < T3)      yo[t0]      = y0;
            if (t0 + 32 < T3) yo[t0 + 32] = y1;
        }
    }
}

// ---- mixer: ow GEMM + GLU(ch) + residual + LN(ch) ----
__global__ __launch_bounds__(256) void k_mix(const float* __restrict__ ow,
                                             const float* __restrict__ ob,
                                             const float* __restrict__ lg,
                                             const float* __restrict__ lb, int lay) {
    __shared__ float Ws[64][130];
    __shared__ float ys[64][32];
    __shared__ float rsum[8][32], rss2[8][32];
    __shared__ float mu[32], rstd[32];
    int b = blockIdx.y, t0 = blockIdx.x * 32;
    int tid = threadIdx.x;
    const float* owl = ow + lay*2*HH*HH;
    const float* obl = ob + lay*2*HH;
    for (int i = tid; i < 2*HH*HH; i += 256) {
        int j = i >> 6, k = i & 63;
        Ws[k][j] = owl[i];
    }
    for (int i = tid; i < HH*32; i += 256) {
        int ch = i >> 5, tt = i & 31;
        int t = t0 + tt;
        ys[ch][tt] = (t < T3) ? g_y[(b*HH + ch)*T3 + t] : 0.f;
    }
    __syncthreads();
    int chgrp = tid >> 3, tgrp = tid & 7;
    int ch0 = chgrp * 2, tsub = tgrp * 4;
    ull accA[4], accB[4];
    {
        ull ia = pk2(obl[ch0],      obl[ch0 + 1]);
        ull ib = pk2(obl[ch0 + 64], obl[ch0 + 65]);
#pragma unroll
        for (int t = 0; t < 4; t++) { accA[t] = ia; accB[t] = ib; }
    }
#pragma unroll 4
    for (int k = 0; k < 64; k++) {
        ull wa = *(const ull*)&Ws[k][ch0];
        ull wb = *(const ull*)&Ws[k][ch0 + 64];
        float4 yv = *(const float4*)&ys[k][tsub];
        ull y0 = pk2(yv.x, yv.x), y1 = pk2(yv.y, yv.y);
        ull y2 = pk2(yv.z, yv.z), y3 = pk2(yv.w, yv.w);
        accA[0] = ffma2(wa, y0, accA[0]);  accB[0] = ffma2(wb, y0, accB[0]);
        accA[1] = ffma2(wa, y1, accA[1]);  accB[1] = ffma2(wb, y1, accB[1]);
        accA[2] = ffma2(wa, y2, accA[2]);  accB[2] = ffma2(wb, y2, accB[2]);
        accA[3] = ffma2(wa, y3, accA[3]);  accB[3] = ffma2(wb, y3, accB[3]);
    }
    __syncthreads();
    float zr0[4], zr1[4];
#pragma unroll
    for (int t = 0; t < 4; t++) {
        int tg = t0 + tsub + t;
        float oa0, oa1, og0, og1;
        upk2(accA[t], oa0, oa1);
        upk2(accB[t], og0, og1);
        float h0 = 0.f, h1 = 0.f;
        if (tg < T3) {
            h0 = g_h[(b*HH + ch0)*T3 + tg];
            h1 = g_h[(b*HH + ch0 + 1)*T3 + tg];
        }
        float z0 = oa0 / (1.f + __expf(-og0)) + h0;
        float z1 = oa1 / (1.f + __expf(-og1)) + h1;
        zr0[t] = z0; zr1[t] = z1;
        ys[ch0][tsub + t]     = z0;
        ys[ch0 + 1][tsub + t] = z1;
    }
    __syncthreads();
    {
        int grp = tid >> 5, tsel = tid & 31;
        float s = 0.f, ss = 0.f;
#pragma unroll
        for (int q = 0; q < 8; q++) {
            float v = ys[grp*8 + q][tsel];
            s += v; ss += v*v;
        }
        rsum[grp][tsel] = s; rss2[grp][tsel] = ss;
    }
    __syncthreads();
    if (tid < 32) {
        float s = 0.f, ss = 0.f;
#pragma unroll
        for (int g = 0; g < 8; g++) { s += rsum[g][tid]; ss += rss2[g][tid]; }
        float m = s / 64.f;
        float var = ss / 64.f - m*m;
        mu[tid] = m; rstd[tid] = rsqrtf(var + EPSF);
    }
    __syncthreads();
    float lg0 = lg[lay*HH + ch0], lg1 = lg[lay*HH + ch0 + 1];
    float lb0 = lb[lay*HH + ch0], lb1 = lb[lay*HH + ch0 + 1];
#pragma unroll
    for (int t = 0; t < 4; t++) {
        int tg = t0 + tsub + t;
        if (tg < T3) {
            float m = mu[tsub + t], rr = rstd[tsub + t];
            g_h[(b*HH + ch0)*T3 + tg]     = (zr0[t] - m) * rr * lg0 + lb0;
            g_h[(b*HH + ch0 + 1)*T3 + tg] = (zr1[t] - m) * rr * lg1 + lb1;
        }
    }
}

// ---------------- decoder ----------------
__global__ __launch_bounds__(256) void k_dec(const float* __restrict__ dw,
                                             const float* __restrict__ db,
                                             float* __restrict__ out) {
    __shared__ float wsd[HH][64];
    __shared__ float hsd[HH][64];
    int o0b = blockIdx.x * 64, t0 = blockIdx.y * 64, b = blockIdx.z;
    int tid = threadIdx.x;
    for (int i = tid; i < HH*64; i += 256) {
        int d = i >> 6, o = i & 63;
        wsd[d][o] = dw[d*DOUT + o0b + o];
    }
    for (int i = tid; i < HH*64; i += 256) {
        int d = i >> 6, tt = i & 63;
        int t = t0 + tt;
        hsd[d][tt] = (t < T3) ? g_h[(b*HH + d)*T3 + t] : 0.f;
    }
    __syncthreads();
    int ogrp = tid & 15, tgrp = tid >> 4;
    int o0 = ogrp * 4, tsub = tgrp * 4;
    ull accA[4], accB[4];
    {
        ull ia = pk2(db[o0b + o0],     db[o0b + o0 + 1]);
        ull ib = pk2(db[o0b + o0 + 2], db[o0b + o0 + 3]);
#pragma unroll
        for (int t = 0; t < 4; t++) { accA[t] = ia; accB[t] = ib; }
    }
#pragma unroll 4
    for (int k = 0; k < HH; k++) {
        ull wa = *(const ull*)&wsd[k][o0];
        ull wb = *(const ull*)&wsd[k][o0 + 2];
        float4 hv = *(const float4*)&hsd[k][tsub];
        ull h0 = pk2(hv.x, hv.x), h1 = pk2(hv.y, hv.y);
        ull h2 = pk2(hv.z, hv.z), h3 = pk2(hv.w, hv.w);
        accA[0] = ffma2(wa, h0, accA[0]);  accB[0] = ffma2(wb, h0, accB[0]);
        accA[1] = ffma2(wa, h1, accA[1]);  accB[1] = ffma2(wb, h1, accB[1]);
        accA[2] = ffma2(wa, h2, accA[2]);  accB[2] = ffma2(wb, h2, accB[2]);
        accA[3] = ffma2(wa, h3, accA[3]);  accB[3] = ffma2(wb, h3, accB[3]);
    }
#pragma unroll
    for (int t = 0; t < 4; t++) {
        int tg = t0 + tsub + t;
        if (tg < T3) {
            float4 o4;
            upk2(accA[t], o4.x, o4.y);
            upk2(accB[t], o4.z, o4.w);
            *(float4*)&out[((size_t)(b*T3 + tg))*DOUT + o0b + o0] = o4;
        }
    }
}

// ---------------- launcher ----------------
extern "C" void kernel_launch(void* const* d_in, const int* in_sizes, int n_in,
                              void* d_out, int out_size) {
    const float* x      = (const float*)d_in[0];
    const float* pw1w   = (const float*)d_in[1];
    const float* pw1b   = (const float*)d_in[2];
    const float* gn1g   = (const float*)d_in[3];
    const float* gn1b   = (const float*)d_in[4];
    const float* dww    = (const float*)d_in[5];
    const float* dwb    = (const float*)d_in[6];
    const float* gn2g   = (const float*)d_in[7];
    const float* gn2b   = (const float*)d_in[8];
    const float* pw2w   = (const float*)d_in[9];
    const float* pw2b   = (const float*)d_in[10];
    const float* encw   = (const float*)d_in[11];
    const float* encb   = (const float*)d_in[12];
    const float* logdt  = (const float*)d_in[13];
    const float* logA   = (const float*)d_in[14];
    const float* Aim    = (const float*)d_in[15];
    const float* Cre    = (const float*)d_in[16];
    const float* Cim    = (const float*)d_in[17];
    const float* s4D    = (const float*)d_in[18];
    const float* s4ow   = (const float*)d_in[19];
    const float* s4ob   = (const float*)d_in[20];
    const float* lng    = (const float*)d_in[21];
    const float* lnb    = (const float*)d_in[22];
    const float* decw   = (const float*)d_in[23];
    const float* decb   = (const float*)d_in[24];
    float* out = (float*)d_out;

    static int smem_set = 0;
    if (!smem_set) {
        cudaFuncSetAttribute(k_sc2, cudaFuncAttributeMaxDynamicSharedMemorySize,
                             SM_TOT * 4);
        smem_set = 1;
    }

    k_s4c<<<dim3(HH, NL), 64>>>(logdt, logA, Aim, Cre, Cim, s4D);
    k_pw1<<<dim3(T1/128, BB), 256>>>(x, pw1w, pw1b);
    k_dwf<<<dim3(2, CO, BB), 256>>>(dww, dwb, gn1g, gn1b);
    k_prep<<<9, 256>>>(pw2w, pw2b, encw, encb);
    k_enc<<<dim3(16, BB), 256>>>(gn2g, gn2b);
    for (int l = 0; l < NL; l++) {
        k_sc2<<<BB*HH, 320, SM_TOT*4>>>(l);
        k_mix<<<dim3(64, BB), 256>>>(s4ow, s4ob, lng, lnb, l);
    }
    k_dec<<<dim3(DOUT/64, 32, BB), 256>>>(decw, decb, out);
}

// round 13
// speedup vs baseline: 1.4092x; 1.4092x over previous
#include <cuda_runtime.h>
#include <math.h>

typedef unsigned long long ull;

// ---------------- problem constants ----------------
#define BB   16
#define C1   64
#define T1   4096
#define CO   32
#define T2   2048      // after GLU over time
#define T3   2019      // after depthwise conv k=32, pad(1,1)
#define HH   64        // d_model
#define NST  64        // S4 state size
#define NL   8
#define DOUT 640
#define EPSF 1e-5f
#define SEG  128       // scan segment length
#define NSEG 16
#define NPOW 15        // carries/powers: segments 0..14

// ---------------- f32x2 packed helpers ----------------
__device__ __forceinline__ ull pk2(float a, float b) {
    ull r; asm("mov.b64 %0, {%1, %2};" : "=l"(r) : "f"(a), "f"(b)); return r;
}
__device__ __forceinline__ void upk2(ull v, float& a, float& b) {
    asm("mov.b64 {%0, %1}, %2;" : "=f"(a), "=f"(b) : "l"(v));
}
__device__ __forceinline__ ull ffma2(ull a, ull b, ull c) {
    ull r; asm("fma.rn.f32x2 %0, %1, %2, %3;" : "=l"(r) : "l"(a), "l"(b), "l"(c)); return r;
}
__device__ __forceinline__ ull fmul2(ull a, ull b) {
    ull r; asm("mul.rn.f32x2 %0, %1, %2;" : "=l"(r) : "l"(a), "l"(b)); return r;
}
__device__ __forceinline__ ull fadd2(ull a, ull b) {
    ull r; asm("add.rn.f32x2 %0, %1, %2;" : "=l"(r) : "l"(a), "l"(b)); return r;
}

// ---------------- scratch (device globals; no allocation) ----------------
__device__ float g_u1[BB*CO*T1];
__device__ float g_u2[BB*CO*T3];
__device__ float g_h [BB*HH*T3];
__device__ float g_y [BB*HH*T3];
__device__ float g_st1[BB*2];
__device__ float g_st2[BB*2];
__device__ float g_Wm [HH*CO];
__device__ float g_bv [HH];

__device__ ull g_pAr [NL*HH*32];
__device__ ull g_pAi [NL*HH*32];
__device__ ull g_pAin[NL*HH*32];
__device__ ull g_pCr [NL*HH*32];
__device__ ull g_pCi [NL*HH*32];
__device__ ull g_pCin[NL*HH*32];
__device__ ull g_aPr [NL*HH*NPOW*32];
__device__ ull g_aPi [NL*HH*NPOW*32];
__device__ ull g_aPin[NL*HH*NPOW*32];
__device__ ull g_carR[NPOW*BB*HH*32];
__device__ ull g_carI[NPOW*BB*HH*32];
__device__ int g_flag[NL*NPOW*BB*HH];

// ---------------- S4D constants + power tables + flag/stat zero ----------------
__global__ void k_s4c(const float* __restrict__ logdt, const float* __restrict__ logA,
                      const float* __restrict__ Aim,  const float* __restrict__ Cre,
                      const float* __restrict__ Cim) {
    __shared__ float s_ar[64], s_ai[64], s_cr[64], s_ci[64];
    __shared__ float s_pr[NPOW][64], s_pi[NPOW][64];
    int h = blockIdx.x, lay = blockIdx.y, n = threadIdx.x;
    if (h == 0 && lay == 0 && n < BB*2) { g_st1[n] = 0.f; g_st2[n] = 0.f; }
    {   // zero publish flags every launch/replay
        int gidx = (lay*HH + h)*64 + n;
        for (int i = gidx; i < NL*NPOW*BB*HH; i += NL*HH*64) g_flag[i] = 0;
    }
    int src = (lay*HH + h)*NST + n;
    float dt  = expf(logdt[lay*HH + h]);
    float Are = -expf(logA[src]);
    float Aii = Aim[src];
    float e = expf(Are * dt);
    float are = e * cosf(Aii * dt);
    float aim = e * sinf(Aii * dt);
    float nre = are - 1.f, nim = aim;
    float den = Are*Are + Aii*Aii;
    float qre = (nre*Are + nim*Aii) / den;
    float qim = (nim*Are - nre*Aii) / den;
    float cre = Cre[src], cim = Cim[src];
    s_ar[n] = are; s_ai[n] = aim;
    s_cr[n] = 2.f*(cre*qre - cim*qim);
    s_ci[n] = 2.f*(cre*qim + cim*qre);
    // a^128 via 7 squarings
    float qr = are, qi = aim;
#pragma unroll
    for (int s = 0; s < 7; s++) {
        float nr = qr*qr - qi*qi, ni = 2.f*qr*qi;
        qr = nr; qi = ni;
    }
    float Pr = 1.f, Pi = 0.f;
    s_pr[0][n] = 1.f; s_pi[0][n] = 0.f;
#pragma unroll
    for (int k = 1; k < NPOW; k++) {
        float nr = Pr*qr - Pi*qi, ni = Pr*qi + Pi*qr;
        Pr = nr; Pi = ni;
        s_pr[k][n] = Pr; s_pi[k][n] = Pi;
    }
    __syncthreads();
    if (n < 32) {
        int base = (lay*HH + h)*32 + n;
        g_pAr [base] = pk2(s_ar[n],  s_ar[n+32]);
        g_pAi [base] = pk2(s_ai[n],  s_ai[n+32]);
        g_pAin[base] = pk2(-s_ai[n], -s_ai[n+32]);
        g_pCr [base] = pk2(s_cr[n],  s_cr[n+32]);
        g_pCi [base] = pk2(s_ci[n],  s_ci[n+32]);
        g_pCin[base] = pk2(-s_ci[n], -s_ci[n+32]);
#pragma unroll
        for (int k = 0; k < NPOW; k++) {
            int bp = ((lay*HH + h)*NPOW + k)*32 + n;
            g_aPr [bp] = pk2(s_pr[k][n],  s_pr[k][n+32]);
            g_aPi [bp] = pk2(s_pi[k][n],  s_pi[k][n+32]);
            g_aPin[bp] = pk2(-s_pi[k][n], -s_pi[k][n+32]);
        }
    }
}

// ---------------- pw1 (64->32 pointwise, packed) + GN1 stats ----------------
__global__ __launch_bounds__(256) void k_pw1(const float* __restrict__ x,
                                             const float* __restrict__ w,
                                             const float* __restrict__ bias) {
    __shared__ float xs[C1][128];
    __shared__ float wst[C1][34];
    __shared__ float rs[8], rss[8];
    int b = blockIdx.y, t0 = blockIdx.x * 128;
    int tid = threadIdx.x;
    for (int i = tid; i < C1*128; i += 256) {
        int c = i >> 7, tt = i & 127;
        xs[c][tt] = x[(b*C1 + c)*T1 + t0 + tt];
    }
    for (int i = tid; i < CO*C1; i += 256) {
        int o = i >> 6, c = i & 63;
        wst[c][o] = w[i];
    }
    __syncthreads();
    int tt = tid & 127, half = tid >> 7;
    int ob0 = half * 16;
    ull acc[8];
#pragma unroll
    for (int p = 0; p < 8; p++) acc[p] = pk2(bias[ob0 + 2*p], bias[ob0 + 2*p + 1]);
    for (int c = 0; c < C1; c++) {
        float xv = xs[c][tt];
        ull X = pk2(xv, xv);
#pragma unroll
        for (int p = 0; p < 8; p++) {
            ull wv = *(const ull*)&wst[c][ob0 + 2*p];
            acc[p] = ffma2(wv, X, acc[p]);
        }
    }
    float s = 0.f, ss = 0.f;
#pragma unroll
    for (int p = 0; p < 8; p++) {
        float a0, a1; upk2(acc[p], a0, a1);
        int o = ob0 + 2*p;
        g_u1[(b*CO + o)*T1 + t0 + tt]     = a0;
        g_u1[(b*CO + o + 1)*T1 + t0 + tt] = a1;
        s += a0 + a1; ss += a0*a0 + a1*a1;
    }
#pragma unroll
    for (int off = 16; off; off >>= 1) {
        s  += __shfl_xor_sync(0xffffffffu, s,  off);
        ss += __shfl_xor_sync(0xffffffffu, ss, off);
    }
    int wid = tid >> 5;
    if ((tid & 31) == 0) { rs[wid] = s; rss[wid] = ss; }
    __syncthreads();
    if (tid == 0) {
        float a = 0.f, q = 0.f;
        for (int i = 0; i < 8; i++) { a += rs[i]; q += rss[i]; }
        atomicAdd(&g_st1[b*2],     a);
        atomicAdd(&g_st1[b*2 + 1], q);
    }
}

// ---- fused GN1-apply + GLU(time) + SiLU + depthwise conv (k=32) + GN2 stats ----
__global__ __launch_bounds__(256) void k_dwf(const float* __restrict__ w,
                                             const float* __restrict__ bias,
                                             const float* __restrict__ g1,
                                             const float* __restrict__ b1) {
    __shared__ float us[1024 + 36];
    __shared__ float wk[32];
    __shared__ float rs[8], rss[8];
    int t0 = blockIdx.x * 1024, c = blockIdx.y, b = blockIdx.z;
    int tid = threadIdx.x;
    if (tid < 32) wk[tid] = w[c*32 + tid];
    float n1 = (float)(CO * T1);
    float m1   = g_st1[b*2] / n1;
    float var1 = g_st1[b*2 + 1] / n1 - m1*m1;
    float rstd1 = rsqrtf(var1 + EPSF);
    float sc = rstd1 * g1[c], sh = b1[c] - m1 * sc;
    const float* base = g_u1 + (b*CO + c)*T1;
    for (int i = tid; i < 1060; i += 256) {
        int gi = t0 - 1 + i;
        float v = 0.f;
        if (gi >= 0 && gi < T2) {
            float ga = fmaf(base[gi],      sc, sh);
            float gb = fmaf(base[gi + T2], sc, sh);
            v = ga / (1.f + __expf(-gb));
            v = v / (1.f + __expf(-v));
        }
        us[i] = v;
    }
    __syncthreads();
    int tt = tid * 4;
    float uw[36];
#pragma unroll
    for (int q = 0; q < 9; q++) {
        float4 v = *(const float4*)&us[tt + q*4];
        uw[q*4+0] = v.x; uw[q*4+1] = v.y; uw[q*4+2] = v.z; uw[q*4+3] = v.w;
    }
    float bc = bias[c];
    float a0 = bc, a1 = bc, a2 = bc, a3 = bc;
#pragma unroll
    for (int k = 0; k < 32; k++) {
        float wv = wk[k];
        a0 = fmaf(wv, uw[k],     a0);
        a1 = fmaf(wv, uw[k + 1], a1);
        a2 = fmaf(wv, uw[k + 2], a2);
        a3 = fmaf(wv, uw[k + 3], a3);
    }
    float s = 0.f, ss = 0.f;
    float* dst = g_u2 + (b*CO + c)*T3 + t0 + tt;
    float av[4] = {a0, a1, a2, a3};
#pragma unroll
    for (int r = 0; r < 4; r++) {
        int t = t0 + tt + r;
        if (t < T3) { dst[r] = av[r]; s += av[r]; ss += av[r]*av[r]; }
    }
#pragma unroll
    for (int off = 16; off; off >>= 1) {
        s  += __shfl_xor_sync(0xffffffffu, s,  off);
        ss += __shfl_xor_sync(0xffffffffu, ss, off);
    }
    int wid = tid >> 5;
    if ((tid & 31) == 0) { rs[wid] = s; rss[wid] = ss; }
    __syncthreads();
    if (tid == 0) {
        float a = 0.f, q = 0.f;
        for (int i = 0; i < 8; i++) { a += rs[i]; q += rss[i]; }
        atomicAdd(&g_st2[b*2],     a);
        atomicAdd(&g_st2[b*2 + 1], q);
    }
}

// ---------------- fused (enc ∘ pw2) matrix ----------------
__global__ __launch_bounds__(256) void k_prep(const float* __restrict__ pw2w,
                                              const float* __restrict__ pw2b,
                                              const float* __restrict__ encw,
                                              const float* __restrict__ encb) {
    int i = blockIdx.x * 256 + threadIdx.x;
    if (i < HH*CO) {
        int d = i >> 5, cp = i & 31;
        float acc = 0.f;
#pragma unroll 8
        for (int c = 0; c < CO; c++)
            acc = fmaf(encw[c*HH + d], pw2w[c*CO + cp], acc);
        g_Wm[i] = acc;
    } else if (i < HH*CO + HH) {
        int d = i - HH*CO;
        float acc = encb[d];
#pragma unroll 8
        for (int c = 0; c < CO; c++)
            acc = fmaf(encw[c*HH + d], pw2b[c], acc);
        g_bv[d] = acc;
    }
}

// ---------------- GN2 apply + fused pw2∘enc -> h ----------------
__global__ __launch_bounds__(256) void k_enc(const float* __restrict__ g2,
                                             const float* __restrict__ b2) {
    __shared__ float un[CO][128];
    __shared__ float Wse[CO][66];
    int b = blockIdx.y, t0 = blockIdx.x * 128;
    int tid = threadIdx.x;
    float n = (float)(CO * T3);
    float m   = g_st2[b*2] / n;
    float var = g_st2[b*2 + 1] / n - m*m;
    float rstd = rsqrtf(var + EPSF);
    for (int i = tid; i < CO*128; i += 256) {
        int c = i >> 7, tt = i & 127;
        int t = t0 + tt;
        float v = (t < T3) ? g_u2[(b*CO + c)*T3 + t] : 0.f;
        un[c][tt] = (v - m) * rstd * g2[c] + b2[c];
    }
    for (int i = tid; i < HH*CO; i += 256) {
        int d = i >> 5, c = i & 31;
        Wse[c][d] = g_Wm[i];
    }
    __syncthreads();
    int tt = tid & 127, dg = tid >> 7;
    int d0 = dg * 32;
    ull acc[16];
#pragma unroll
    for (int p = 0; p < 16; p++) acc[p] = pk2(g_bv[d0 + 2*p], g_bv[d0 + 2*p + 1]);
    for (int c = 0; c < CO; c++) {
        float uv = un[c][tt];
        ull U = pk2(uv, uv);
#pragma unroll
        for (int p = 0; p < 16; p++) {
            ull wv = *(const ull*)&Wse[c][d0 + 2*p];
            acc[p] = ffma2(wv, U, acc[p]);
        }
    }
    int t = t0 + tt;
    if (t < T3) {
#pragma unroll
        for (int p = 0; p < 16; p++) {
            float a0, a1; upk2(acc[p], a0, a1);
            g_h[(b*HH + d0 + 2*p)*T3 + t]     = a0;
            g_h[(b*HH + d0 + 2*p + 1)*T3 + t] = a1;
        }
    }
}

// ---------------- fused S4D scan: carry + flags + z-form output ----------------
__global__ __launch_bounds__(128) void k_sc(const float* __restrict__ D, int lay) {
    __shared__ ull ps[4][32*33];     // packed partials per warp
    __shared__ ull up[4][SEG];       // (u,u) pairs per warp
    int lane = threadIdx.x & 31, wl = threadIdx.x >> 5;
    int wg = blockIdx.x * 4 + wl;            // 0..16383
    int bh = wg & 1023, p = wg >> 10;        // seg p in 0..15
    int b = bh >> 6, h = bh & 63;
    int cbase = (lay*HH + h)*32 + lane;
    ull Ar  = g_pAr [cbase];
    ull Ai  = g_pAi [cbase];
    ull NAi = g_pAin[cbase];
    ull CcR = g_pCr [cbase];
    ull CcI = g_pCi [cbase];
    ull CcIn= g_pCin[cbase];
    float Dh = D[lay*HH + h];
    int t0 = p * SEG;
    int len = min(SEG, T3 - t0);             // 128, or 99 for p=15
    const float* uin = g_h + (b*HH + h)*T3 + t0;
    float* yo = g_y + (b*HH + h)*T3 + t0;
    ull* upw = up[wl];
    float u[4];
#pragma unroll
    for (int ci = 0; ci < 4; ci++) {
        int t = ci*32 + lane;
        u[ci] = (t < len) ? uin[t] : 0.f;
        upw[t] = pk2(u[ci], u[ci]);
    }
    __syncwarp();
    // ---- phase 1: compute + publish carry (segments 0..14) ----
    if (p < NPOW) {
        ull Sr = 0ull, Si = 0ull;
#pragma unroll
        for (int ci = 0; ci < 4; ci++) {
#pragma unroll
            for (int j = 0; j < 32; j++) {
                ull U = upw[ci*32 + j];
                ull t = ffma2(NAi, Si, U);
                ull m = fmul2(Ai, Sr);
                Sr = ffma2(Ar, Sr, t);
                Si = ffma2(Ar, Si, m);
            }
        }
        int ci2 = (p*BB*HH + bh)*32 + lane;
        g_carR[ci2] = Sr;
        g_carI[ci2] = Si;
        __syncwarp();
        __threadfence();
        if (lane == 0)
            *((volatile int*)&g_flag[(lay*NPOW + p)*BB*HH + bh]) = 1;
    }
    // ---- wait for predecessors ----
    for (int q = 0; q < p; q++) {
        volatile int* f = &g_flag[(lay*NPOW + q)*BB*HH + bh];
        while (*f == 0) __nanosleep(64);
    }
    __threadfence();
    // ---- reconstruct segment-start state ----
    ull Sr = 0ull, Si = 0ull;
    for (int q = 0; q < p; q++) {
        int k = p - 1 - q;
        int bp = ((lay*HH + h)*NPOW + k)*32 + lane;
        ull aPr  = g_aPr [bp];
        ull aPi  = g_aPi [bp];
        ull aPin = g_aPin[bp];
        int ci2 = (q*BB*HH + bh)*32 + lane;
        ull CqR = g_carR[ci2], CqI = g_carI[ci2];
        Sr = ffma2(aPr,  CqR, Sr);
        Sr = ffma2(aPin, CqI, Sr);
        Si = ffma2(aPr,  CqI, Si);
        Si = ffma2(aPi,  CqR, Si);
    }
    ull zr = ffma2(CcR, Sr, fmul2(CcIn, Si));
    ull zi = ffma2(CcR, Si, fmul2(CcI,  Sr));
    ull* psw = ps[wl];
    // ---- phase 2: output scan ----
#pragma unroll
    for (int ci = 0; ci < 4; ci++) {
        int lc = len - ci*32;
        if (lc >= 32) {
#pragma unroll
            for (int j = 0; j < 32; j++) {
                ull U = upw[ci*32 + j];
                ull t1 = ffma2(NAi, zi, fmul2(CcR, U));
                ull t3 = ffma2(Ai,  zr, fmul2(CcI, U));
                zr = ffma2(Ar, zr, t1);
                zi = ffma2(Ar, zi, t3);
                psw[lane*33 + j] = zr;
            }
            __syncwarp();
            ull acc0 = psw[lane];
            ull acc1 = psw[33 + lane];
#pragma unroll
            for (int k = 2; k < 32; k += 2) {
                acc0 = fadd2(acc0, psw[k*33 + lane]);
                acc1 = fadd2(acc1, psw[(k+1)*33 + lane]);
            }
            ull acc = fadd2(acc0, acc1);
            float plo, phi; upk2(acc, plo, phi);
            float yv = fmaf(Dh, u[ci], plo + phi);
            yv = 0.5f * yv * (1.f + erff(yv * 0.70710678118f));
            yo[ci*32 + lane] = yv;
            __syncwarp();
        } else if (lc > 0) {
            for (int j = 0; j < lc; j++) {
                ull U = upw[ci*32 + j];
                ull t1 = ffma2(NAi, zi, fmul2(CcR, U));
                ull t3 = ffma2(Ai,  zr, fmul2(CcI, U));
                zr = ffma2(Ar, zr, t1);
                zi = ffma2(Ar, zi, t3);
                psw[lane*33 + j] = zr;
            }
            __syncwarp();
            if (lane < lc) {
                ull acc = psw[lane];
#pragma unroll
                for (int k = 1; k < 32; k++) acc = fadd2(acc, psw[k*33 + lane]);
                float plo, phi; upk2(acc, plo, phi);
                float yv = fmaf(Dh, u[ci], plo + phi);
                yv = 0.5f * yv * (1.f + erff(yv * 0.70710678118f));
                yo[ci*32 + lane] = yv;
            }
            __syncwarp();
        }
    }
}

// ---- mixer: smem-tiled ow GEMM (packed) + GLU(ch) + residual + LN(ch) ----
__global__ __launch_bounds__(256) void k_mix(const float* __restrict__ ow,
                                             const float* __restrict__ ob,
                                             const float* __restrict__ lg,
                                             const float* __restrict__ lb, int lay) {
    __shared__ float Ws[64][130];
    __shared__ float ys[64][32];
    __shared__ float rsum[8][32], rss2[8][32];
    __shared__ float mu[32], rstd[32];
    int b = blockIdx.y, t0 = blockIdx.x * 32;
    int tid = threadIdx.x;
    const float* owl = ow + lay*2*HH*HH;
    const float* obl = ob + lay*2*HH;
    for (int i = tid; i < 2*HH*HH; i += 256) {
        int j = i >> 6, k = i & 63;
        Ws[k][j] = owl[i];
    }
    for (int i = tid; i < HH*32; i += 256) {
        int ch = i >> 5, tt = i & 31;
        int t = t0 + tt;
        ys[ch][tt] = (t < T3) ? g_y[(b*HH + ch)*T3 + t] : 0.f;
    }
    __syncthreads();
    int chgrp = tid >> 3, tgrp = tid & 7;
    int ch0 = chgrp * 2, tsub = tgrp * 4;
    ull accA[4], accB[4];
    {
        ull ia = pk2(obl[ch0],      obl[ch0 + 1]);
        ull ib = pk2(obl[ch0 + 64], obl[ch0 + 65]);
#pragma unroll
        for (int t = 0; t < 4; t++) { accA[t] = ia; accB[t] = ib; }
    }
#pragma unroll 4
    for (int k = 0; k < 64; k++) {
        ull wa = *(const ull*)&Ws[k][ch0];
        ull wb = *(const ull*)&Ws[k][ch0 + 64];
        float4 yv = *(const float4*)&ys[k][tsub];
        ull y0 = pk2(yv.x, yv.x), y1 = pk2(yv.y, yv.y);
        ull y2 = pk2(yv.z, yv.z), y3 = pk2(yv.w, yv.w);
        accA[0] = ffma2(wa, y0, accA[0]);  accB[0] = ffma2(wb, y0, accB[0]);
        accA[1] = ffma2(wa, y1, accA[1]);  accB[1] = ffma2(wb, y1, accB[1]);
        accA[2] = ffma2(wa, y2, accA[2]);  accB[2] = ffma2(wb, y2, accB[2]);
        accA[3] = ffma2(wa, y3, accA[3]);  accB[3] = ffma2(wb, y3, accB[3]);
    }
    __syncthreads();
    float zr0[4], zr1[4];
#pragma unroll
    for (int t = 0; t < 4; t++) {
        int tg = t0 + tsub + t;
        float oa0, oa1, og0, og1;
        upk2(accA[t], oa0, oa1);
        upk2(accB[t], og0, og1);
        float h0 = 0.f, h1 = 0.f;
        if (tg < T3) {
            h0 = g_h[(b*HH + ch0)*T3 + tg];
            h1 = g_h[(b*HH + ch0 + 1)*T3 + tg];
        }
        float z0 = oa0 / (1.f + __expf(-og0)) + h0;
        float z1 = oa1 / (1.f + __expf(-og1)) + h1;
        zr0[t] = z0; zr1[t] = z1;
        ys[ch0][tsub + t]     = z0;
        ys[ch0 + 1][tsub + t] = z1;
    }
    __syncthreads();
    {
        int grp = tid >> 5, tsel = tid & 31;
        float s = 0.f, ss = 0.f;
#pragma unroll
        for (int q = 0; q < 8; q++) {
            float v = ys[grp*8 + q][tsel];
            s += v; ss += v*v;
        }
        rsum[grp][tsel] = s; rss2[grp][tsel] = ss;
    }
    __syncthreads();
    if (tid < 32) {
        float s = 0.f, ss = 0.f;
#pragma unroll
        for (int g = 0; g < 8; g++) { s += rsum[g][tid]; ss += rss2[g][tid]; }
        float m = s / 64.f;
        float var = ss / 64.f - m*m;
        mu[tid] = m; rstd[tid] = rsqrtf(var + EPSF);
    }
    __syncthreads();
    float lg0 = lg[lay*HH + ch0], lg1 = lg[lay*HH + ch0 + 1];
    float lb0 = lb[lay*HH + ch0], lb1 = lb[lay*HH + ch0 + 1];
#pragma unroll
    for (int t = 0; t < 4; t++) {
        int tg = t0 + tsub + t;
        if (tg < T3) {
            float m = mu[tsub + t], rr = rstd[tsub + t];
            g_h[(b*HH + ch0)*T3 + tg]     = (zr0[t] - m) * rr * lg0 + lb0;
            g_h[(b*HH + ch0 + 1)*T3 + tg] = (zr1[t] - m) * rr * lg1 + lb1;
        }
    }
}

// ---------------- decoder: tiled packed GEMM ----------------
__global__ __launch_bounds__(256) void k_dec(const float* __restrict__ dw,
                                             const float* __restrict__ db,
                                             float* __restrict__ out) {
    __shared__ float wsd[HH][64];
    __shared__ float hsd[HH][64];
    int o0b = blockIdx.x * 64, t0 = blockIdx.y * 64, b = blockIdx.z;
    int tid = threadIdx.x;
    for (int i = tid; i < HH*64; i += 256) {
        int d = i >> 6, o = i & 63;
        wsd[d][o] = dw[d*DOUT + o0b + o];
    }
    for (int i = tid; i < HH*64; i += 256) {
        int d = i >> 6, tt = i & 63;
        int t = t0 + tt;
        hsd[d][tt] = (t < T3) ? g_h[(b*HH + d)*T3 + t] : 0.f;
    }
    __syncthreads();
    int ogrp = tid & 15, tgrp = tid >> 4;
    int o0 = ogrp * 4, tsub = tgrp * 4;
    ull accA[4], accB[4];
    {
        ull ia = pk2(db[o0b + o0],     db[o0b + o0 + 1]);
        ull ib = pk2(db[o0b + o0 + 2], db[o0b + o0 + 3]);
#pragma unroll
        for (int t = 0; t < 4; t++) { accA[t] = ia; accB[t] = ib; }
    }
#pragma unroll 4
    for (int k = 0; k < HH; k++) {
        ull wa = *(const ull*)&wsd[k][o0];
        ull wb = *(const ull*)&wsd[k][o0 + 2];
        float4 hv = *(const float4*)&hsd[k][tsub];
        ull h0 = pk2(hv.x, hv.x), h1 = pk2(hv.y, hv.y);
        ull h2 = pk2(hv.z, hv.z), h3 = pk2(hv.w, hv.w);
        accA[0] = ffma2(wa, h0, accA[0]);  accB[0] = ffma2(wb, h0, accB[0]);
        accA[1] = ffma2(wa, h1, accA[1]);  accB[1] = ffma2(wb, h1, accB[1]);
        accA[2] = ffma2(wa, h2, accA[2]);  accB[2] = ffma2(wb, h2, accB[2]);
        accA[3] = ffma2(wa, h3, accA[3]);  accB[3] = ffma2(wb, h3, accB[3]);
    }
#pragma unroll
    for (int t = 0; t < 4; t++) {
        int tg = t0 + tsub + t;
        if (tg < T3) {
            float4 o4;
            upk2(accA[t], o4.x, o4.y);
            upk2(accB[t], o4.z, o4.w);
            *(float4*)&out[((size_t)(b*T3 + tg))*DOUT + o0b + o0] = o4;
        }
    }
}

// ---------------- launcher ----------------
extern "C" void kernel_launch(void* const* d_in, const int* in_sizes, int n_in,
                              void* d_out, int out_size) {
    const float* x      = (const float*)d_in[0];
    const float* pw1w   = (const float*)d_in[1];
    const float* pw1b   = (const float*)d_in[2];
    const float* gn1g   = (const float*)d_in[3];
    const float* gn1b   = (const float*)d_in[4];
    const float* dww    = (const float*)d_in[5];
    const float* dwb    = (const float*)d_in[6];
    const float* gn2g   = (const float*)d_in[7];
    const float* gn2b   = (const float*)d_in[8];
    const float* pw2w   = (const float*)d_in[9];
    const float* pw2b   = (const float*)d_in[10];
    const float* encw   = (const float*)d_in[11];
    const float* encb   = (const float*)d_in[12];
    const float* logdt  = (const float*)d_in[13];
    const float* logA   = (const float*)d_in[14];
    const float* Aim    = (const float*)d_in[15];
    const float* Cre    = (const float*)d_in[16];
    const float* Cim    = (const float*)d_in[17];
    const float* s4D    = (const float*)d_in[18];
    const float* s4ow   = (const float*)d_in[19];
    const float* s4ob   = (const float*)d_in[20];
    const float* lng    = (const float*)d_in[21];
    const float* lnb    = (const float*)d_in[22];
    const float* decw   = (const float*)d_in[23];
    const float* decb   = (const float*)d_in[24];
    float* out = (float*)d_out;

    k_s4c<<<dim3(HH, NL), 64>>>(logdt, logA, Aim, Cre, Cim);
    k_pw1<<<dim3(T1/128, BB), 256>>>(x, pw1w, pw1b);
    k_dwf<<<dim3(2, CO, BB), 256>>>(dww, dwb, gn1g, gn1b);
    k_prep<<<9, 256>>>(pw2w, pw2b, encw, encb);
    k_enc<<<dim3(16, BB), 256>>>(gn2g, gn2b);
    for (int l = 0; l < NL; l++) {
        k_sc<<<(BB*HH*NSEG)/4, 128>>>(s4D, l);
        k_mix<<<dim3(64, BB), 256>>>(s4ow, s4ob, lng, lnb, l);
    }
    k_dec<<<dim3(DOUT/64, 32, BB), 256>>>(decw, decb, out);
}

// round 14
// speedup vs baseline: 1.4532x; 1.0312x over previous
#include <cuda_runtime.h>
#include <math.h>

typedef unsigned long long ull;

// ---------------- problem constants ----------------
#define BB   16
#define C1   64
#define T1   4096
#define CO   32
#define T2   2048      // after GLU over time
#define T3   2019      // after depthwise conv k=32, pad(1,1)
#define HH   64        // d_model
#define NST  64        // S4 state size
#define NL   8
#define DOUT 640
#define EPSF 1e-5f
#define SEG  256       // scan segment length
#define NSEG 8

// ---------------- f32x2 packed helpers ----------------
__device__ __forceinline__ ull pk2(float a, float b) {
    ull r; asm("mov.b64 %0, {%1, %2};" : "=l"(r) : "f"(a), "f"(b)); return r;
}
__device__ __forceinline__ void upk2(ull v, float& a, float& b) {
    asm("mov.b64 {%0, %1}, %2;" : "=f"(a), "=f"(b) : "l"(v));
}
__device__ __forceinline__ ull ffma2(ull a, ull b, ull c) {
    ull r; asm("fma.rn.f32x2 %0, %1, %2, %3;" : "=l"(r) : "l"(a), "l"(b), "l"(c)); return r;
}
__device__ __forceinline__ ull fmul2(ull a, ull b) {
    ull r; asm("mul.rn.f32x2 %0, %1, %2;" : "=l"(r) : "l"(a), "l"(b)); return r;
}
__device__ __forceinline__ ull fadd2(ull a, ull b) {
    ull r; asm("add.rn.f32x2 %0, %1, %2;" : "=l"(r) : "l"(a), "l"(b)); return r;
}

// ---------------- scratch (device globals; no allocation) ----------------
__device__ float g_u1[BB*CO*T1];
__device__ float g_u2[BB*CO*T3];
__device__ float g_h [BB*HH*T3];
__device__ float g_y [BB*HH*T3];
__device__ float g_st1[BB*2];
__device__ float g_st2[BB*2];
__device__ float g_Wm [HH*CO];
__device__ float g_bv [HH];

__device__ ull g_pAr [NL*HH*32];
__device__ ull g_pAi [NL*HH*32];
__device__ ull g_pAin[NL*HH*32];
__device__ ull g_pCr [NL*HH*32];
__device__ ull g_pCi [NL*HH*32];
__device__ ull g_pCin[NL*HH*32];
__device__ ull g_aPr [NL*HH*7*32];
__device__ ull g_aPi [NL*HH*7*32];
__device__ ull g_aPin[NL*HH*7*32];
__device__ ull g_carR[7*BB*HH*32];
__device__ ull g_carI[7*BB*HH*32];
__device__ int g_flag[NL*7*BB*HH];    // publish flags per (lay, seg 0..6, bh)

// ---------------- S4D constants + power tables + flag/stat zero ----------------
__global__ void k_s4c(const float* __restrict__ logdt, const float* __restrict__ logA,
                      const float* __restrict__ Aim,  const float* __restrict__ Cre,
                      const float* __restrict__ Cim) {
    __shared__ float s_ar[64], s_ai[64], s_cr[64], s_ci[64];
    __shared__ float s_pr[7][64], s_pi[7][64];
    int h = blockIdx.x, lay = blockIdx.y, n = threadIdx.x;
    if (h == 0 && lay == 0 && n < BB*2) { g_st1[n] = 0.f; g_st2[n] = 0.f; }
    {   // zero the publish flags (every launch / replay)
        int gidx = (lay*HH + h)*64 + n;
        for (int i = gidx; i < NL*7*BB*HH; i += NL*HH*64) g_flag[i] = 0;
    }
    int src = (lay*HH + h)*NST + n;
    float dt  = expf(logdt[lay*HH + h]);
    float Are = -expf(logA[src]);
    float Aii = Aim[src];
    float e = expf(Are * dt);
    float are = e * cosf(Aii * dt);
    float aim = e * sinf(Aii * dt);
    float nre = are - 1.f, nim = aim;
    float den = Are*Are + Aii*Aii;
    float qre = (nre*Are + nim*Aii) / den;
    float qim = (nim*Are - nre*Aii) / den;
    float cre = Cre[src], cim = Cim[src];
    s_ar[n] = are; s_ai[n] = aim;
    s_cr[n] = 2.f*(cre*qre - cim*qim);
    s_ci[n] = 2.f*(cre*qim + cim*qre);
    float qr = are, qi = aim;
#pragma unroll
    for (int s = 0; s < 8; s++) {
        float nr = qr*qr - qi*qi, ni = 2.f*qr*qi;
        qr = nr; qi = ni;
    }
    float Pr = 1.f, Pi = 0.f;
    s_pr[0][n] = 1.f; s_pi[0][n] = 0.f;
#pragma unroll
    for (int k = 1; k < 7; k++) {
        float nr = Pr*qr - Pi*qi, ni = Pr*qi + Pi*qr;
        Pr = nr; Pi = ni;
        s_pr[k][n] = Pr; s_pi[k][n] = Pi;
    }
    __syncthreads();
    if (n < 32) {
        int base = (lay*HH + h)*32 + n;
        g_pAr [base] = pk2(s_ar[n],  s_ar[n+32]);
        g_pAi [base] = pk2(s_ai[n],  s_ai[n+32]);
        g_pAin[base] = pk2(-s_ai[n], -s_ai[n+32]);
        g_pCr [base] = pk2(s_cr[n],  s_cr[n+32]);
        g_pCi [base] = pk2(s_ci[n],  s_ci[n+32]);
        g_pCin[base] = pk2(-s_ci[n], -s_ci[n+32]);
#pragma unroll
        for (int k = 0; k < 7; k++) {
            int bp = ((lay*HH + h)*7 + k)*32 + n;
            g_aPr [bp] = pk2(s_pr[k][n],  s_pr[k][n+32]);
            g_aPi [bp] = pk2(s_pi[k][n],  s_pi[k][n+32]);
            g_aPin[bp] = pk2(-s_pi[k][n], -s_pi[k][n+32]);
        }
    }
}

// ---------------- pw1 (64->32 pointwise, packed) + GN1 stats ----------------
__global__ __launch_bounds__(256) void k_pw1(const float* __restrict__ x,
                                             const float* __restrict__ w,
                                             const float* __restrict__ bias) {
    __shared__ float xs[C1][128];
    __shared__ float wst[C1][34];
    __shared__ float rs[8], rss[8];
    int b = blockIdx.y, t0 = blockIdx.x * 128;
    int tid = threadIdx.x;
    for (int i = tid; i < C1*128; i += 256) {
        int c = i >> 7, tt = i & 127;
        xs[c][tt] = x[(b*C1 + c)*T1 + t0 + tt];
    }
    for (int i = tid; i < CO*C1; i += 256) {
        int o = i >> 6, c = i & 63;
        wst[c][o] = w[i];
    }
    __syncthreads();
    int tt = tid & 127, half = tid >> 7;
    int ob0 = half * 16;
    ull acc[8];
#pragma unroll
    for (int p = 0; p < 8; p++) acc[p] = pk2(bias[ob0 + 2*p], bias[ob0 + 2*p + 1]);
    for (int c = 0; c < C1; c++) {
        float xv = xs[c][tt];
        ull X = pk2(xv, xv);
#pragma unroll
        for (int p = 0; p < 8; p++) {
            ull wv = *(const ull*)&wst[c][ob0 + 2*p];
            acc[p] = ffma2(wv, X, acc[p]);
        }
    }
    float s = 0.f, ss = 0.f;
#pragma unroll
    for (int p = 0; p < 8; p++) {
        float a0, a1; upk2(acc[p], a0, a1);
        int o = ob0 + 2*p;
        g_u1[(b*CO + o)*T1 + t0 + tt]     = a0;
        g_u1[(b*CO + o + 1)*T1 + t0 + tt] = a1;
        s += a0 + a1; ss += a0*a0 + a1*a1;
    }
#pragma unroll
    for (int off = 16; off; off >>= 1) {
        s  += __shfl_xor_sync(0xffffffffu, s,  off);
        ss += __shfl_xor_sync(0xffffffffu, ss, off);
    }
    int wid = tid >> 5;
    if ((tid & 31) == 0) { rs[wid] = s; rss[wid] = ss; }
    __syncthreads();
    if (tid == 0) {
        float a = 0.f, q = 0.f;
        for (int i = 0; i < 8; i++) { a += rs[i]; q += rss[i]; }
        atomicAdd(&g_st1[b*2],     a);
        atomicAdd(&g_st1[b*2 + 1], q);
    }
}

// ---- fused GN1-apply + GLU(time) + SiLU + depthwise conv (k=32) + GN2 stats ----
__global__ __launch_bounds__(256) void k_dwf(const float* __restrict__ w,
                                             const float* __restrict__ bias,
                                             const float* __restrict__ g1,
                                             const float* __restrict__ b1) {
    __shared__ float us[1024 + 36];
    __shared__ float wk[32];
    __shared__ float rs[8], rss[8];
    int t0 = blockIdx.x * 1024, c = blockIdx.y, b = blockIdx.z;
    int tid = threadIdx.x;
    if (tid < 32) wk[tid] = w[c*32 + tid];
    float n1 = (float)(CO * T1);
    float m1   = g_st1[b*2] / n1;
    float var1 = g_st1[b*2 + 1] / n1 - m1*m1;
    float rstd1 = rsqrtf(var1 + EPSF);
    float sc = rstd1 * g1[c], sh = b1[c] - m1 * sc;
    const float* base = g_u1 + (b*CO + c)*T1;
    for (int i = tid; i < 1060; i += 256) {
        int gi = t0 - 1 + i;
        float v = 0.f;
        if (gi >= 0 && gi < T2) {
            float ga = fmaf(base[gi],      sc, sh);
            float gb = fmaf(base[gi + T2], sc, sh);
            v = ga / (1.f + __expf(-gb));
            v = v / (1.f + __expf(-v));
        }
        us[i] = v;
    }
    __syncthreads();
    int tt = tid * 4;
    float uw[36];
#pragma unroll
    for (int q = 0; q < 9; q++) {
        float4 v = *(const float4*)&us[tt + q*4];
        uw[q*4+0] = v.x; uw[q*4+1] = v.y; uw[q*4+2] = v.z; uw[q*4+3] = v.w;
    }
    float bc = bias[c];
    float a0 = bc, a1 = bc, a2 = bc, a3 = bc;
#pragma unroll
    for (int k = 0; k < 32; k++) {
        float wv = wk[k];
        a0 = fmaf(wv, uw[k],     a0);
        a1 = fmaf(wv, uw[k + 1], a1);
        a2 = fmaf(wv, uw[k + 2], a2);
        a3 = fmaf(wv, uw[k + 3], a3);
    }
    float s = 0.f, ss = 0.f;
    float* dst = g_u2 + (b*CO + c)*T3 + t0 + tt;
    float av[4] = {a0, a1, a2, a3};
#pragma unroll
    for (int r = 0; r < 4; r++) {
        int t = t0 + tt + r;
        if (t < T3) { dst[r] = av[r]; s += av[r]; ss += av[r]*av[r]; }
    }
#pragma unroll
    for (int off = 16; off; off >>= 1) {
        s  += __shfl_xor_sync(0xffffffffu, s,  off);
        ss += __shfl_xor_sync(0xffffffffu, ss, off);
    }
    int wid = tid >> 5;
    if ((tid & 31) == 0) { rs[wid] = s; rss[wid] = ss; }
    __syncthreads();
    if (tid == 0) {
        float a = 0.f, q = 0.f;
        for (int i = 0; i < 8; i++) { a += rs[i]; q += rss[i]; }
        atomicAdd(&g_st2[b*2],     a);
        atomicAdd(&g_st2[b*2 + 1], q);
    }
}

// ---------------- fused (enc ∘ pw2) matrix ----------------
__global__ __launch_bounds__(256) void k_prep(const float* __restrict__ pw2w,
                                              const float* __restrict__ pw2b,
                                              const float* __restrict__ encw,
                                              const float* __restrict__ encb) {
    int i = blockIdx.x * 256 + threadIdx.x;
    if (i < HH*CO) {
        int d = i >> 5, cp = i & 31;
        float acc = 0.f;
#pragma unroll 8
        for (int c = 0; c < CO; c++)
            acc = fmaf(encw[c*HH + d], pw2w[c*CO + cp], acc);
        g_Wm[i] = acc;
    } else if (i < HH*CO + HH) {
        int d = i - HH*CO;
        float acc = encb[d];
#pragma unroll 8
        for (int c = 0; c < CO; c++)
            acc = fmaf(encw[c*HH + d], pw2b[c], acc);
        g_bv[d] = acc;
    }
}

// ---------------- GN2 apply + fused pw2∘enc -> h ----------------
__global__ __launch_bounds__(256) void k_enc(const float* __restrict__ g2,
                                             const float* __restrict__ b2) {
    __shared__ float un[CO][128];
    __shared__ float Wse[CO][66];
    int b = blockIdx.y, t0 = blockIdx.x * 128;
    int tid = threadIdx.x;
    float n = (float)(CO * T3);
    float m   = g_st2[b*2] / n;
    float var = g_st2[b*2 + 1] / n - m*m;
    float rstd = rsqrtf(var + EPSF);
    for (int i = tid; i < CO*128; i += 256) {
        int c = i >> 7, tt = i & 127;
        int t = t0 + tt;
        float v = (t < T3) ? g_u2[(b*CO + c)*T3 + t] : 0.f;
        un[c][tt] = (v - m) * rstd * g2[c] + b2[c];
    }
    for (int i = tid; i < HH*CO; i += 256) {
        int d = i >> 5, c = i & 31;
        Wse[c][d] = g_Wm[i];
    }
    __syncthreads();
    int tt = tid & 127, dg = tid >> 7;
    int d0 = dg * 32;
    ull acc[16];
#pragma unroll
    for (int p = 0; p < 16; p++) acc[p] = pk2(g_bv[d0 + 2*p], g_bv[d0 + 2*p + 1]);
    for (int c = 0; c < CO; c++) {
        float uv = un[c][tt];
        ull U = pk2(uv, uv);
#pragma unroll
        for (int p = 0; p < 16; p++) {
            ull wv = *(const ull*)&Wse[c][d0 + 2*p];
            acc[p] = ffma2(wv, U, acc[p]);
        }
    }
    int t = t0 + tt;
    if (t < T3) {
#pragma unroll
        for (int p = 0; p < 16; p++) {
            float a0, a1; upk2(acc[p], a0, a1);
            g_h[(b*HH + d0 + 2*p)*T3 + t]     = a0;
            g_h[(b*HH + d0 + 2*p + 1)*T3 + t] = a1;
        }
    }
}

// ---------------- fused S4D scan: carry + flags + z-form output ----------------
// u pre-paired in smem (LDS.64 broadcast); packed ull partials (conflict-free:
// 64-bit smem ops run as two 16-lane phases; ull-stride 33 ≡ 1 mod 16).
__global__ __launch_bounds__(128) void k_sc(const float* __restrict__ D, int lay) {
    __shared__ ull ps[4][32*33];     // packed zr partials per warp (33.8KB total)
    __shared__ ull up[4][SEG];       // (u,u) pairs per warp (8KB total)
    int lane = threadIdx.x & 31, wl = threadIdx.x >> 5;
    int wg = blockIdx.x * 4 + wl;            // 0..8191
    int bh = wg & 1023, p = wg >> 10;        // seg p in 0..7
    int b = bh >> 6, h = bh & 63;
    int cbase = (lay*HH + h)*32 + lane;
    ull Ar  = g_pAr [cbase];
    ull Ai  = g_pAi [cbase];
    ull NAi = g_pAin[cbase];
    ull CcR = g_pCr [cbase];
    ull CcI = g_pCi [cbase];
    ull CcIn= g_pCin[cbase];
    float Dh = D[lay*HH + h];
    int t0 = p * SEG;
    int len = min(SEG, T3 - t0);             // 256, or 227 for p=7
    const float* uin = g_h + (b*HH + h)*T3 + t0;
    float* yo = g_y + (b*HH + h)*T3 + t0;
    ull* upw = up[wl];
    float u[8];
#pragma unroll
    for (int ci = 0; ci < 8; ci++) {
        int t = ci*32 + lane;
        u[ci] = (t < len) ? uin[t] : 0.f;
        upw[t] = pk2(u[ci], u[ci]);
    }
    __syncwarp();
    // ---- phase 1: compute + publish this segment's carry (segments 0..6) ----
    if (p < 7) {
        ull Sr = 0ull, Si = 0ull;
#pragma unroll
        for (int ci = 0; ci < 8; ci++) {
#pragma unroll
            for (int j = 0; j < 32; j++) {
                ull U = upw[ci*32 + j];
                ull t = ffma2(NAi, Si, U);
                ull m = fmul2(Ai, Sr);
                Sr = ffma2(Ar, Sr, t);
                Si = ffma2(Ar, Si, m);
            }
        }
        int ci2 = (p*BB*HH + bh)*32 + lane;
        g_carR[ci2] = Sr;
        g_carI[ci2] = Si;
        __syncwarp();
        __threadfence();
        if (lane == 0)
            *((volatile int*)&g_flag[(lay*7 + p)*BB*HH + bh]) = 1;
    }
    // ---- wait for predecessors' carries ----
    for (int q = 0; q < p; q++) {
        volatile int* f = &g_flag[(lay*7 + q)*BB*HH + bh];
        while (*f == 0) __nanosleep(64);
    }
    __threadfence();
    // ---- reconstruct segment-start state ----
    ull Sr = 0ull, Si = 0ull;
    for (int q = 0; q < p; q++) {
        int k = p - 1 - q;
        int bp = ((lay*HH + h)*7 + k)*32 + lane;
        ull aPr  = g_aPr [bp];
        ull aPi  = g_aPi [bp];
        ull aPin = g_aPin[bp];
        int ci2 = (q*BB*HH + bh)*32 + lane;
        ull CqR = g_carR[ci2], CqI = g_carI[ci2];
        Sr = ffma2(aPr,  CqR, Sr);
        Sr = ffma2(aPin, CqI, Sr);
        Si = ffma2(aPr,  CqI, Si);
        Si = ffma2(aPi,  CqR, Si);
    }
    // z = Cc ⊙ S
    ull zr = ffma2(CcR, Sr, fmul2(CcIn, Si));
    ull zi = ffma2(CcR, Si, fmul2(CcI,  Sr));
    ull* psw = ps[wl];
    // ---- phase 2: output scan, chunks 0..6 always full ----
#pragma unroll
    for (int ci = 0; ci < 7; ci++) {
#pragma unroll
        for (int j = 0; j < 32; j++) {
            ull U = upw[ci*32 + j];
            ull t1 = ffma2(NAi, zi, fmul2(CcR, U));
            ull t3 = ffma2(Ai,  zr, fmul2(CcI, U));
            zr = ffma2(Ar, zr, t1);
            zi = ffma2(Ar, zi, t3);
            psw[lane*33 + j] = zr;
        }
        __syncwarp();
        {
            ull acc0 = psw[lane];
            ull acc1 = psw[33 + lane];
#pragma unroll
            for (int k = 2; k < 32; k += 2) {
                acc0 = fadd2(acc0, psw[k*33 + lane]);
                acc1 = fadd2(acc1, psw[(k+1)*33 + lane]);
            }
            ull acc = fadd2(acc0, acc1);
            float plo, phi; upk2(acc, plo, phi);
            float yv = fmaf(Dh, u[ci], plo + phi);
            yv = 0.5f * yv * (1.f + erff(yv * 0.70710678118f));
            yo[ci*32 + lane] = yv;
        }
        __syncwarp();
    }
    // ---- tail chunk 7 (lc = 32 or 3) ----
    {
        int lc = len - 224;
        for (int j = 0; j < lc; j++) {
            ull U = upw[224 + j];
            ull t1 = ffma2(NAi, zi, fmul2(CcR, U));
            ull t3 = ffma2(Ai,  zr, fmul2(CcI, U));
            zr = ffma2(Ar, zr, t1);
            zi = ffma2(Ar, zi, t3);
            psw[lane*33 + j] = zr;
        }
        __syncwarp();
        if (lane < lc) {
            ull acc = psw[lane];
#pragma unroll
            for (int k = 1; k < 32; k++) acc = fadd2(acc, psw[k*33 + lane]);
            float plo, phi; upk2(acc, plo, phi);
            float yv = fmaf(Dh, u[7], plo + phi);
            yv = 0.5f * yv * (1.f + erff(yv * 0.70710678118f));
            yo[224 + lane] = yv;
        }
    }
}

// ---- mixer: smem-tiled ow GEMM (packed) + GLU(ch) + residual + LN(ch) ----
__global__ __launch_bounds__(256) void k_mix(const float* __restrict__ ow,
                                             const float* __restrict__ ob,
                                             const float* __restrict__ lg,
                                             const float* __restrict__ lb, int lay) {
    __shared__ float Ws[64][130];
    __shared__ float ys[64][32];
    __shared__ float rsum[8][32], rss2[8][32];
    __shared__ float mu[32], rstd[32];
    int b = blockIdx.y, t0 = blockIdx.x * 32;
    int tid = threadIdx.x;
    const float* owl = ow + lay*2*HH*HH;
    const float* obl = ob + lay*2*HH;
    for (int i = tid; i < 2*HH*HH; i += 256) {
        int j = i >> 6, k = i & 63;
        Ws[k][j] = owl[i];
    }
    for (int i = tid; i < HH*32; i += 256) {
        int ch = i >> 5, tt = i & 31;
        int t = t0 + tt;
        ys[ch][tt] = (t < T3) ? g_y[(b*HH + ch)*T3 + t] : 0.f;
    }
    __syncthreads();
    int chgrp = tid >> 3, tgrp = tid & 7;
    int ch0 = chgrp * 2, tsub = tgrp * 4;
    ull accA[4], accB[4];
    {
        ull ia = pk2(obl[ch0],      obl[ch0 + 1]);
        ull ib = pk2(obl[ch0 + 64], obl[ch0 + 65]);
#pragma unroll
        for (int t = 0; t < 4; t++) { accA[t] = ia; accB[t] = ib; }
    }
#pragma unroll 4
    for (int k = 0; k < 64; k++) {
        ull wa = *(const ull*)&Ws[k][ch0];
        ull wb = *(const ull*)&Ws[k][ch0 + 64];
        float4 yv = *(const float4*)&ys[k][tsub];
        ull y0 = pk2(yv.x, yv.x), y1 = pk2(yv.y, yv.y);
        ull y2 = pk2(yv.z, yv.z), y3 = pk2(yv.w, yv.w);
        accA[0] = ffma2(wa, y0, accA[0]);  accB[0] = ffma2(wb, y0, accB[0]);
        accA[1] = ffma2(wa, y1, accA[1]);  accB[1] = ffma2(wb, y1, accB[1]);
        accA[2] = ffma2(wa, y2, accA[2]);  accB[2] = ffma2(wb, y2, accB[2]);
        accA[3] = ffma2(wa, y3, accA[3]);  accB[3] = ffma2(wb, y3, accB[3]);
    }
    __syncthreads();
    float zr0[4], zr1[4];
#pragma unroll
    for (int t = 0; t < 4; t++) {
        int tg = t0 + tsub + t;
        float oa0, oa1, og0, og1;
        upk2(accA[t], oa0, oa1);
        upk2(accB[t], og0, og1);
        float h0 = 0.f, h1 = 0.f;
        if (tg < T3) {
            h0 = g_h[(b*HH + ch0)*T3 + tg];
            h1 = g_h[(b*HH + ch0 + 1)*T3 + tg];
        }
        float z0 = oa0 / (1.f + __expf(-og0)) + h0;
        float z1 = oa1 / (1.f + __expf(-og1)) + h1;
        zr0[t] = z0; zr1[t] = z1;
        ys[ch0][tsub + t]     = z0;
        ys[ch0 + 1][tsub + t] = z1;
    }
    __syncthreads();
    {
        int grp = tid >> 5, tsel = tid & 31;
        float s = 0.f, ss = 0.f;
#pragma unroll
        for (int q = 0; q < 8; q++) {
            float v = ys[grp*8 + q][tsel];
            s += v; ss += v*v;
        }
        rsum[grp][tsel] = s; rss2[grp][tsel] = ss;
    }
    __syncthreads();
    if (tid < 32) {
        float s = 0.f, ss = 0.f;
#pragma unroll
        for (int g = 0; g < 8; g++) { s += rsum[g][tid]; ss += rss2[g][tid]; }
        float m = s / 64.f;
        float var = ss / 64.f - m*m;
        mu[tid] = m; rstd[tid] = rsqrtf(var + EPSF);
    }
    __syncthreads();
    float lg0 = lg[lay*HH + ch0], lg1 = lg[lay*HH + ch0 + 1];
    float lb0 = lb[lay*HH + ch0], lb1 = lb[lay*HH + ch0 + 1];
#pragma unroll
    for (int t = 0; t < 4; t++) {
        int tg = t0 + tsub + t;
        if (tg < T3) {
            float m = mu[tsub + t], rr = rstd[tsub + t];
            g_h[(b*HH + ch0)*T3 + tg]     = (zr0[t] - m) * rr * lg0 + lb0;
            g_h[(b*HH + ch0 + 1)*T3 + tg] = (zr1[t] - m) * rr * lg1 + lb1;
        }
    }
}

// ---------------- decoder: tiled packed GEMM ----------------
__global__ __launch_bounds__(256) void k_dec(const float* __restrict__ dw,
                                             const float* __restrict__ db,
                                             float* __restrict__ out) {
    __shared__ float wsd[HH][64];
    __shared__ float hsd[HH][64];
    int o0b = blockIdx.x * 64, t0 = blockIdx.y * 64, b = blockIdx.z;
    int tid = threadIdx.x;
    for (int i = tid; i < HH*64; i += 256) {
        int d = i >> 6, o = i & 63;
        wsd[d][o] = dw[d*DOUT + o0b + o];
    }
    for (int i = tid; i < HH*64; i += 256) {
        int d = i >> 6, tt = i & 63;
        int t = t0 + tt;
        hsd[d][tt] = (t < T3) ? g_h[(b*HH + d)*T3 + t] : 0.f;
    }
    __syncthreads();
    int ogrp = tid & 15, tgrp = tid >> 4;
    int o0 = ogrp * 4, tsub = tgrp * 4;
    ull accA[4], accB[4];
    {
        ull ia = pk2(db[o0b + o0],     db[o0b + o0 + 1]);
        ull ib = pk2(db[o0b + o0 + 2], db[o0b + o0 + 3]);
#pragma unroll
        for (int t = 0; t < 4; t++) { accA[t] = ia; accB[t] = ib; }
    }
#pragma unroll 4
    for (int k = 0; k < HH; k++) {
        ull wa = *(const ull*)&wsd[k][o0];
        ull wb = *(const ull*)&wsd[k][o0 + 2];
        float4 hv = *(const float4*)&hsd[k][tsub];
        ull h0 = pk2(hv.x, hv.x), h1 = pk2(hv.y, hv.y);
        ull h2 = pk2(hv.z, hv.z), h3 = pk2(hv.w, hv.w);
        accA[0] = ffma2(wa, h0, accA[0]);  accB[0] = ffma2(wb, h0, accB[0]);
        accA[1] = ffma2(wa, h1, accA[1]);  accB[1] = ffma2(wb, h1, accB[1]);
        accA[2] = ffma2(wa, h2, accA[2]);  accB[2] = ffma2(wb, h2, accB[2]);
        accA[3] = ffma2(wa, h3, accA[3]);  accB[3] = ffma2(wb, h3, accB[3]);
    }
#pragma unroll
    for (int t = 0; t < 4; t++) {
        int tg = t0 + tsub + t;
        if (tg < T3) {
            float4 o4;
            upk2(accA[t], o4.x, o4.y);
            upk2(accB[t], o4.z, o4.w);
            *(float4*)&out[((size_t)(b*T3 + tg))*DOUT + o0b + o0] = o4;
        }
    }
}

// ---------------- launcher ----------------
extern "C" void kernel_launch(void* const* d_in, const int* in_sizes, int n_in,
                              void* d_out, int out_size) {
    const float* x      = (const float*)d_in[0];
    const float* pw1w   = (const float*)d_in[1];
    const float* pw1b   = (const float*)d_in[2];
    const float* gn1g   = (const float*)d_in[3];
    const float* gn1b   = (const float*)d_in[4];
    const float* dww    = (const float*)d_in[5];
    const float* dwb    = (const float*)d_in[6];
    const float* gn2g   = (const float*)d_in[7];
    const float* gn2b   = (const float*)d_in[8];
    const float* pw2w   = (const float*)d_in[9];
    const float* pw2b   = (const float*)d_in[10];
    const float* encw   = (const float*)d_in[11];
    const float* encb   = (const float*)d_in[12];
    const float* logdt  = (const float*)d_in[13];
    const float* logA   = (const float*)d_in[14];
    const float* Aim    = (const float*)d_in[15];
    const float* Cre    = (const float*)d_in[16];
    const float* Cim    = (const float*)d_in[17];
    const float* s4D    = (const float*)d_in[18];
    const float* s4ow   = (const float*)d_in[19];
    const float* s4ob   = (const float*)d_in[20];
    const float* lng    = (const float*)d_in[21];
    const float* lnb    = (const float*)d_in[22];
    const float* decw   = (const float*)d_in[23];
    const float* decb   = (const float*)d_in[24];
    float* out = (float*)d_out;

    k_s4c<<<dim3(HH, NL), 64>>>(logdt, logA, Aim, Cre, Cim);
    k_pw1<<<dim3(T1/128, BB), 256>>>(x, pw1w, pw1b);
    k_dwf<<<dim3(2, CO, BB), 256>>>(dww, dwb, gn1g, gn1b);
    k_prep<<<9, 256>>>(pw2w, pw2b, encw, encb);
    k_enc<<<dim3(16, BB), 256>>>(gn2g, gn2b);
    for (int l = 0; l < NL; l++) {
        k_sc<<<(BB*HH*NSEG)/4, 128>>>(s4D, l);
        k_mix<<<dim3(64, BB), 256>>>(s4ow, s4ob, lng, lnb, l);
    }
    k_dec<<<dim3(DOUT/64, 32, BB), 256>>>(decw, decb, out);
}

// round 16
// speedup vs baseline: 1.4731x; 1.0137x over previous
#include <cuda_runtime.h>
#include <math.h>

typedef unsigned long long ull;

// ---------------- problem constants ----------------
#define BB   16
#define C1   64
#define T1   4096
#define CO   32
#define T2   2048      // after GLU over time
#define T3   2019      // after depthwise conv k=32, pad(1,1)
#define HH   64        // d_model
#define NST  64        // S4 state size
#define NL   8
#define DOUT 640
#define EPSF 1e-5f
#define SEG  256       // scan segment length
#define NSEG 8

// ---------------- f32x2 packed helpers ----------------
__device__ __forceinline__ ull pk2(float a, float b) {
    ull r; asm("mov.b64 %0, {%1, %2};" : "=l"(r) : "f"(a), "f"(b)); return r;
}
__device__ __forceinline__ void upk2(ull v, float& a, float& b) {
    asm("mov.b64 {%0, %1}, %2;" : "=f"(a), "=f"(b) : "l"(v));
}
__device__ __forceinline__ ull ffma2(ull a, ull b, ull c) {
    ull r; asm("fma.rn.f32x2 %0, %1, %2, %3;" : "=l"(r) : "l"(a), "l"(b), "l"(c)); return r;
}
__device__ __forceinline__ ull fmul2(ull a, ull b) {
    ull r; asm("mul.rn.f32x2 %0, %1, %2;" : "=l"(r) : "l"(a), "l"(b)); return r;
}

// ---------------- scratch (device globals; no allocation) ----------------
__device__ float g_u1[BB*CO*T1];
__device__ float g_u2[BB*CO*T3];
__device__ float g_h [BB*HH*T3];
__device__ float g_y [BB*HH*T3];
__device__ float g_st1[BB*2];
__device__ float g_st2[BB*2];
__device__ float g_Wm [HH*CO];
__device__ float g_bv [HH];

__device__ ull g_pAr [NL*HH*32];
__device__ ull g_pAi [NL*HH*32];
__device__ ull g_pAin[NL*HH*32];
__device__ ull g_pCr [NL*HH*32];
__device__ ull g_pCi [NL*HH*32];
__device__ ull g_pCin[NL*HH*32];
__device__ ull g_aPr [NL*HH*7*32];
__device__ ull g_aPi [NL*HH*7*32];
__device__ ull g_aPin[NL*HH*7*32];
__device__ ull g_carR[7*BB*HH*32];
__device__ ull g_carI[7*BB*HH*32];
__device__ int g_flag[NL*7*BB*HH];    // publish flags per (lay, seg 0..6, bh)

// ---------------- S4D constants + power tables + flag/stat zero ----------------
__global__ void k_s4c(const float* __restrict__ logdt, const float* __restrict__ logA,
                      const float* __restrict__ Aim,  const float* __restrict__ Cre,
                      const float* __restrict__ Cim) {
    __shared__ float s_ar[64], s_ai[64], s_cr[64], s_ci[64];
    __shared__ float s_pr[7][64], s_pi[7][64];
    int h = blockIdx.x, lay = blockIdx.y, n = threadIdx.x;
    if (h == 0 && lay == 0 && n < BB*2) { g_st1[n] = 0.f; g_st2[n] = 0.f; }
    {
        int gidx = (lay*HH + h)*64 + n;
        for (int i = gidx; i < NL*7*BB*HH; i += NL*HH*64) g_flag[i] = 0;
    }
    int src = (lay*HH + h)*NST + n;
    float dt  = expf(logdt[lay*HH + h]);
    float Are = -expf(logA[src]);
    float Aii = Aim[src];
    float e = expf(Are * dt);
    float are = e * cosf(Aii * dt);
    float aim = e * sinf(Aii * dt);
    float nre = are - 1.f, nim = aim;
    float den = Are*Are + Aii*Aii;
    float qre = (nre*Are + nim*Aii) / den;
    float qim = (nim*Are - nre*Aii) / den;
    float cre = Cre[src], cim = Cim[src];
    s_ar[n] = are; s_ai[n] = aim;
    s_cr[n] = 2.f*(cre*qre - cim*qim);
    s_ci[n] = 2.f*(cre*qim + cim*qre);
    float qr = are, qi = aim;
#pragma unroll
    for (int s = 0; s < 8; s++) {
        float nr = qr*qr - qi*qi, ni = 2.f*qr*qi;
        qr = nr; qi = ni;
    }
    float Pr = 1.f, Pi = 0.f;
    s_pr[0][n] = 1.f; s_pi[0][n] = 0.f;
#pragma unroll
    for (int k = 1; k < 7; k++) {
        float nr = Pr*qr - Pi*qi, ni = Pr*qi + Pi*qr;
        Pr = nr; Pi = ni;
        s_pr[k][n] = Pr; s_pi[k][n] = Pi;
    }
    __syncthreads();
    if (n < 32) {
        int base = (lay*HH + h)*32 + n;
        g_pAr [base] = pk2(s_ar[n],  s_ar[n+32]);
        g_pAi [base] = pk2(s_ai[n],  s_ai[n+32]);
        g_pAin[base] = pk2(-s_ai[n], -s_ai[n+32]);
        g_pCr [base] = pk2(s_cr[n],  s_cr[n+32]);
        g_pCi [base] = pk2(s_ci[n],  s_ci[n+32]);
        g_pCin[base] = pk2(-s_ci[n], -s_ci[n+32]);
#pragma unroll
        for (int k = 0; k < 7; k++) {
            int bp = ((lay*HH + h)*7 + k)*32 + n;
            g_aPr [bp] = pk2(s_pr[k][n],  s_pr[k][n+32]);
            g_aPi [bp] = pk2(s_pi[k][n],  s_pi[k][n+32]);
            g_aPin[bp] = pk2(-s_pi[k][n], -s_pi[k][n+32]);
        }
    }
}

// ---------------- pw1 (64->32 pointwise, packed) + GN1 stats ----------------
__global__ __launch_bounds__(256) void k_pw1(const float* __restrict__ x,
                                             const float* __restrict__ w,
                                             const float* __restrict__ bias) {
    __shared__ float xs[C1][128];
    __shared__ float wst[C1][34];
    __shared__ float rs[8], rss[8];
    int b = blockIdx.y, t0 = blockIdx.x * 128;
    int tid = threadIdx.x;
    for (int i = tid; i < C1*128; i += 256) {
        int c = i >> 7, tt = i & 127;
        xs[c][tt] = x[(b*C1 + c)*T1 + t0 + tt];
    }
    for (int i = tid; i < CO*C1; i += 256) {
        int o = i >> 6, c = i & 63;
        wst[c][o] = w[i];
    }
    __syncthreads();
    int tt = tid & 127, half = tid >> 7;
    int ob0 = half * 16;
    ull acc[8];
#pragma unroll
    for (int p = 0; p < 8; p++) acc[p] = pk2(bias[ob0 + 2*p], bias[ob0 + 2*p + 1]);
    for (int c = 0; c < C1; c++) {
        float xv = xs[c][tt];
        ull X = pk2(xv, xv);
#pragma unroll
        for (int p = 0; p < 8; p++) {
            ull wv = *(const ull*)&wst[c][ob0 + 2*p];
            acc[p] = ffma2(wv, X, acc[p]);
        }
    }
    float s = 0.f, ss = 0.f;
#pragma unroll
    for (int p = 0; p < 8; p++) {
        float a0, a1; upk2(acc[p], a0, a1);
        int o = ob0 + 2*p;
        g_u1[(b*CO + o)*T1 + t0 + tt]     = a0;
        g_u1[(b*CO + o + 1)*T1 + t0 + tt] = a1;
        s += a0 + a1; ss += a0*a0 + a1*a1;
    }
#pragma unroll
    for (int off = 16; off; off >>= 1) {
        s  += __shfl_xor_sync(0xffffffffu, s,  off);
        ss += __shfl_xor_sync(0xffffffffu, ss, off);
    }
    int wid = tid >> 5;
    if ((tid & 31) == 0) { rs[wid] = s; rss[wid] = ss; }
    __syncthreads();
    if (tid == 0) {
        float a = 0.f, q = 0.f;
        for (int i = 0; i < 8; i++) { a += rs[i]; q += rss[i]; }
        atomicAdd(&g_st1[b*2],     a);
        atomicAdd(&g_st1[b*2 + 1], q);
    }
}

// ---- fused GN1-apply + GLU(time) + SiLU + depthwise conv (k=32) + GN2 stats ----
__global__ __launch_bounds__(256) void k_dwf(const float* __restrict__ w,
                                             const float* __restrict__ bias,
                                             const float* __restrict__ g1,
                                             const float* __restrict__ b1) {
    __shared__ float us[1024 + 36];
    __shared__ float wk[32];
    __shared__ float rs[8], rss[8];
    int t0 = blockIdx.x * 1024, c = blockIdx.y, b = blockIdx.z;
    int tid = threadIdx.x;
    if (tid < 32) wk[tid] = w[c*32 + tid];
    float n1 = (float)(CO * T1);
    float m1   = g_st1[b*2] / n1;
    float var1 = g_st1[b*2 + 1] / n1 - m1*m1;
    float rstd1 = rsqrtf(var1 + EPSF);
    float sc = rstd1 * g1[c], sh = b1[c] - m1 * sc;
    const float* base = g_u1 + (b*CO + c)*T1;
    for (int i = tid; i < 1060; i += 256) {
        int gi = t0 - 1 + i;
        float v = 0.f;
        if (gi >= 0 && gi < T2) {
            float ga = fmaf(base[gi],      sc, sh);
            float gb = fmaf(base[gi + T2], sc, sh);
            v = ga / (1.f + __expf(-gb));
            v = v / (1.f + __expf(-v));
        }
        us[i] = v;
    }
    __syncthreads();
    int tt = tid * 4;
    float uw[36];
#pragma unroll
    for (int q = 0; q < 9; q++) {
        float4 v = *(const float4*)&us[tt + q*4];
        uw[q*4+0] = v.x; uw[q*4+1] = v.y; uw[q*4+2] = v.z; uw[q*4+3] = v.w;
    }
    float bc = bias[c];
    float a0 = bc, a1 = bc, a2 = bc, a3 = bc;
#pragma unroll
    for (int k = 0; k < 32; k++) {
        float wv = wk[k];
        a0 = fmaf(wv, uw[k],     a0);
        a1 = fmaf(wv, uw[k + 1], a1);
        a2 = fmaf(wv, uw[k + 2], a2);
        a3 = fmaf(wv, uw[k + 3], a3);
    }
    float s = 0.f, ss = 0.f;
    float* dst = g_u2 + (b*CO + c)*T3 + t0 + tt;
    float av[4] = {a0, a1, a2, a3};
#pragma unroll
    for (int r = 0; r < 4; r++) {
        int t = t0 + tt + r;
        if (t < T3) { dst[r] = av[r]; s += av[r]; ss += av[r]*av[r]; }
    }
#pragma unroll
    for (int off = 16; off; off >>= 1) {
        s  += __shfl_xor_sync(0xffffffffu, s,  off);
        ss += __shfl_xor_sync(0xffffffffu, ss, off);
    }
    int wid = tid >> 5;
    if ((tid & 31) == 0) { rs[wid] = s; rss[wid] = ss; }
    __syncthreads();
    if (tid == 0) {
        float a = 0.f, q = 0.f;
        for (int i = 0; i < 8; i++) { a += rs[i]; q += rss[i]; }
        atomicAdd(&g_st2[b*2],     a);
        atomicAdd(&g_st2[b*2 + 1], q);
    }
}

// ---------------- fused (enc ∘ pw2) matrix ----------------
__global__ __launch_bounds__(256) void k_prep(const float* __restrict__ pw2w,
                                              const float* __restrict__ pw2b,
                                              const float* __restrict__ encw,
                                              const float* __restrict__ encb) {
    int i = blockIdx.x * 256 + threadIdx.x;
    if (i < HH*CO) {
        int d = i >> 5, cp = i & 31;
        float acc = 0.f;
#pragma unroll 8
        for (int c = 0; c < CO; c++)
            acc = fmaf(encw[c*HH + d], pw2w[c*CO + cp], acc);
        g_Wm[i] = acc;
    } else if (i < HH*CO + HH) {
        int d = i - HH*CO;
        float acc = encb[d];
#pragma unroll 8
        for (int c = 0; c < CO; c++)
            acc = fmaf(encw[c*HH + d], pw2b[c], acc);
        g_bv[d] = acc;
    }
}

// ---------------- GN2 apply + fused pw2∘enc -> h ----------------
__global__ __launch_bounds__(256) void k_enc(const float* __restrict__ g2,
                                             const float* __restrict__ b2) {
    __shared__ float un[CO][128];
    __shared__ float Wse[CO][66];
    int b = blockIdx.y, t0 = blockIdx.x * 128;
    int tid = threadIdx.x;
    float n = (float)(CO * T3);
    float m   = g_st2[b*2] / n;
    float var = g_st2[b*2 + 1] / n - m*m;
    float rstd = rsqrtf(var + EPSF);
    for (int i = tid; i < CO*128; i += 256) {
        int c = i >> 7, tt = i & 127;
        int t = t0 + tt;
        float v = (t < T3) ? g_u2[(b*CO + c)*T3 + t] : 0.f;
        un[c][tt] = (v - m) * rstd * g2[c] + b2[c];
    }
    for (int i = tid; i < HH*CO; i += 256) {
        int d = i >> 5, c = i & 31;
        Wse[c][d] = g_Wm[i];
    }
    __syncthreads();
    int tt = tid & 127, dg = tid >> 7;
    int d0 = dg * 32;
    ull acc[16];
#pragma unroll
    for (int p = 0; p < 16; p++) acc[p] = pk2(g_bv[d0 + 2*p], g_bv[d0 + 2*p + 1]);
    for (int c = 0; c < CO; c++) {
        float uv = un[c][tt];
        ull U = pk2(uv, uv);
#pragma unroll
        for (int p = 0; p < 16; p++) {
            ull wv = *(const ull*)&Wse[c][d0 + 2*p];
            acc[p] = ffma2(wv, U, acc[p]);
        }
    }
    int t = t0 + tt;
    if (t < T3) {
#pragma unroll
        for (int p = 0; p < 16; p++) {
            float a0, a1; upk2(acc[p], a0, a1);
            g_h[(b*HH + d0 + 2*p)*T3 + t]     = a0;
            g_h[(b*HH + d0 + 2*p + 1)*T3 + t] = a1;
        }
    }
}

// ---------------- fused S4D scan (R10 shape): carry + flags + z-form output ----------------
__global__ __launch_bounds__(128) void k_sc(const float* __restrict__ D, int lay) {
    __shared__ float ps[4][32*33];
    int lane = threadIdx.x & 31, wl = threadIdx.x >> 5;
    int wg = blockIdx.x * 4 + wl;            // 0..8191
    int bh = wg & 1023, p = wg >> 10;        // seg p in 0..7
    int b = bh >> 6, h = bh & 63;
    int cbase = (lay*HH + h)*32 + lane;
    ull Ar  = g_pAr [cbase];
    ull Ai  = g_pAi [cbase];
    ull NAi = g_pAin[cbase];
    ull CcR = g_pCr [cbase];
    ull CcI = g_pCi [cbase];
    ull CcIn= g_pCin[cbase];
    float Dh = D[lay*HH + h];
    int t0 = p * SEG;
    int len = min(SEG, T3 - t0);             // 256, or 227 for p=7
    const float* uin = g_h + (b*HH + h)*T3 + t0;
    float* yo = g_y + (b*HH + h)*T3 + t0;
    float u[8];
#pragma unroll
    for (int ci = 0; ci < 8; ci++) {
        int t = ci*32 + lane;
        u[ci] = (t < len) ? uin[t] : 0.f;
    }
    // ---- phase 1: compute + publish this segment's carry (segments 0..6) ----
    if (p < 7) {
        ull Sr = 0ull, Si = 0ull;
#pragma unroll
        for (int ci = 0; ci < 8; ci++) {
            float uc = u[ci];
#pragma unroll
            for (int j = 0; j < 32; j++) {
                float uj = __shfl_sync(0xffffffffu, uc, j);
                ull U = pk2(uj, uj);
                ull t = ffma2(NAi, Si, U);
                ull m = fmul2(Ai, Sr);
                Sr = ffma2(Ar, Sr, t);
                Si = ffma2(Ar, Si, m);
            }
        }
        int ci2 = (p*BB*HH + bh)*32 + lane;
        g_carR[ci2] = Sr;
        g_carI[ci2] = Si;
        __syncwarp();
        __threadfence();
        if (lane == 0)
            *((volatile int*)&g_flag[(lay*7 + p)*BB*HH + bh]) = 1;
    }
    // ---- wait for predecessors' carries ----
    for (int q = 0; q < p; q++) {
        volatile int* f = &g_flag[(lay*7 + q)*BB*HH + bh];
        while (*f == 0) __nanosleep(64);
    }
    __threadfence();
    // ---- reconstruct segment-start state ----
    ull Sr = 0ull, Si = 0ull;
    for (int q = 0; q < p; q++) {
        int k = p - 1 - q;
        int bp = ((lay*HH + h)*7 + k)*32 + lane;
        ull aPr  = g_aPr [bp];
        ull aPi  = g_aPi [bp];
        ull aPin = g_aPin[bp];
        int ci2 = (q*BB*HH + bh)*32 + lane;
        ull CqR = g_carR[ci2], CqI = g_carI[ci2];
        Sr = ffma2(aPr,  CqR, Sr);
        Sr = ffma2(aPin, CqI, Sr);
        Si = ffma2(aPr,  CqI, Si);
        Si = ffma2(aPi,  CqR, Si);
    }
    // z = Cc ⊙ S
    ull zr = ffma2(CcR, Sr, fmul2(CcIn, Si));
    ull zi = ffma2(CcR, Si, fmul2(CcI,  Sr));
    float* psw = ps[wl];
    // ---- phase 2: output scan, chunks 0..6 always full ----
#pragma unroll
    for (int ci = 0; ci < 7; ci++) {
        float uc = u[ci];
#pragma unroll
        for (int j = 0; j < 32; j++) {
            float uj = __shfl_sync(0xffffffffu, uc, j);
            ull U = pk2(uj, uj);
            ull t1 = ffma2(NAi, zi, fmul2(CcR, U));
            ull t3 = ffma2(Ai,  zr, fmul2(CcI, U));
            zr = ffma2(Ar, zr, t1);
            zi = ffma2(Ar, zi, t3);
            float lo, hi; upk2(zr, lo, hi);
            psw[lane*33 + j] = lo + hi;
        }
        __syncwarp();
        {
            float acc = psw[lane];
#pragma unroll
            for (int k = 1; k < 32; k++) acc += psw[k*33 + lane];
            float yv = fmaf(Dh, uc, acc);
            yv = 0.5f * yv * (1.f + erff(yv * 0.70710678118f));
            yo[ci*32 + lane] = yv;
        }
        __syncwarp();
    }
    // ---- tail chunk 7 (lc = 32 or 3) ----
    {
        int lc = len - 224;
        float uc = u[7];
        for (int j = 0; j < lc; j++) {
            float uj = __shfl_sync(0xffffffffu, uc, j);
            ull U = pk2(uj, uj);
            ull t1 = ffma2(NAi, zi, fmul2(CcR, U));
            ull t3 = ffma2(Ai,  zr, fmul2(CcI, U));
            zr = ffma2(Ar, zr, t1);
            zi = ffma2(Ar, zi, t3);
            float lo, hi; upk2(zr, lo, hi);
            psw[lane*33 + j] = lo + hi;
        }
        __syncwarp();
        if (lane < lc) {
            float acc = psw[lane];
#pragma unroll
            for (int k = 1; k < 32; k++) acc += psw[k*33 + lane];
            float yv = fmaf(Dh, uc, acc);
            yv = 0.5f * yv * (1.f + erff(yv * 0.70710678118f));
            yo[224 + lane] = yv;
        }
    }
}

// ---- mixer v2: 64-t tile, t-pair accumulation ----
__global__ __launch_bounds__(256) void k_mix(const float* __restrict__ ow,
                                             const float* __restrict__ ob,
                                             const float* __restrict__ lg,
                                             const float* __restrict__ lb, int lay) {
    __shared__ float Ws[64][130];     // [k][j]
    __shared__ float ys[64][64];      // y tile [ch][t]; reused as z tile
    __shared__ float rsum[4][64], rss2[4][64];
    __shared__ float mu[64], rstd[64];
    int b = blockIdx.y, t0 = blockIdx.x * 64;
    int tid = threadIdx.x;
    const float* owl = ow + lay*2*HH*HH;
    const float* obl = ob + lay*2*HH;
    for (int i = tid; i < 2*HH*HH; i += 256) {
        int j = i >> 6, k = i & 63;
        Ws[k][j] = owl[i];
    }
    for (int i = tid; i < HH*64; i += 256) {
        int ch = i >> 6, tt = i & 63;
        int t = t0 + tt;
        ys[ch][tt] = (t < T3) ? g_y[(b*HH + ch)*T3 + t] : 0.f;
    }
    __syncthreads();
    int chgrp = tid & 31, tgrp = tid >> 5;     // 32 ch-pairs x 8 t-groups
    int ch0 = chgrp * 2, tsub = tgrp * 8;
    ull aA0[4], aA1[4], aB0[4], aB1[4];        // [t-pair], rows ch0/ch0+1, halves A/B
    {
        float b0 = obl[ch0], b1 = obl[ch0 + 1];
        float g0 = obl[ch0 + 64], g1 = obl[ch0 + 65];
        ull i0 = pk2(b0, b0), i1 = pk2(b1, b1);
        ull j0 = pk2(g0, g0), j1 = pk2(g1, g1);
#pragma unroll
        for (int t = 0; t < 4; t++) { aA0[t]=i0; aA1[t]=i1; aB0[t]=j0; aB1[t]=j1; }
    }
#pragma unroll 4
    for (int k = 0; k < 64; k++) {
        ull wpA = *(const ull*)&Ws[k][ch0];
        ull wpB = *(const ull*)&Ws[k][ch0 + 64];
        float wa0, wa1, wb0, wb1;
        upk2(wpA, wa0, wa1); upk2(wpB, wb0, wb1);
        ull WA0 = pk2(wa0, wa0), WA1 = pk2(wa1, wa1);
        ull WB0 = pk2(wb0, wb0), WB1 = pk2(wb1, wb1);
        ulonglong2 yv0 = *(const ulonglong2*)&ys[k][tsub];
        ulonglong2 yv1 = *(const ulonglong2*)&ys[k][tsub + 4];
        aA0[0] = ffma2(WA0, yv0.x, aA0[0]);  aA1[0] = ffma2(WA1, yv0.x, aA1[0]);
        aB0[0] = ffma2(WB0, yv0.x, aB0[0]);  aB1[0] = ffma2(WB1, yv0.x, aB1[0]);
        aA0[1] = ffma2(WA0, yv0.y, aA0[1]);  aA1[1] = ffma2(WA1, yv0.y, aA1[1]);
        aB0[1] = ffma2(WB0, yv0.y, aB0[1]);  aB1[1] = ffma2(WB1, yv0.y, aB1[1]);
        aA0[2] = ffma2(WA0, yv1.x, aA0[2]);  aA1[2] = ffma2(WA1, yv1.x, aA1[2]);
        aB0[2] = ffma2(WB0, yv1.x, aB0[2]);  aB1[2] = ffma2(WB1, yv1.x, aB1[2]);
        aA0[3] = ffma2(WA0, yv1.y, aA0[3]);  aA1[3] = ffma2(WA1, yv1.y, aA1[3]);
        aB0[3] = ffma2(WB0, yv1.y, aB0[3]);  aB1[3] = ffma2(WB1, yv1.y, aB1[3]);
    }
    __syncthreads();                  // ys fully consumed
    // epilogue: GLU + residual -> z (regs + smem reuse of ys)
    float z0[8], z1[8];
    const float* h0p = g_h + (b*HH + ch0)*T3 + t0;
    const float* h1p = h0p + T3;
#pragma unroll
    for (int tp = 0; tp < 4; tp++) {
        int te = tsub + 2*tp;
        float oa0e, oa0o, oa1e, oa1o, og0e, og0o, og1e, og1o;
        upk2(aA0[tp], oa0e, oa0o);  upk2(aA1[tp], oa1e, oa1o);
        upk2(aB0[tp], og0e, og0o);  upk2(aB1[tp], og1e, og1o);
        float h0e = 0.f, h0o = 0.f, h1e = 0.f, h1o = 0.f;
        if (t0 + te < T3)     { h0e = h0p[te];     h1e = h1p[te]; }
        if (t0 + te + 1 < T3) { h0o = h0p[te + 1]; h1o = h1p[te + 1]; }
        float ze0 = oa0e / (1.f + __expf(-og0e)) + h0e;
        float zo0 = oa0o / (1.f + __expf(-og0o)) + h0o;
        float ze1 = oa1e / (1.f + __expf(-og1e)) + h1e;
        float zo1 = oa1o / (1.f + __expf(-og1o)) + h1o;
        z0[2*tp] = ze0; z0[2*tp+1] = zo0;
        z1[2*tp] = ze1; z1[2*tp+1] = zo1;
        ys[ch0][te]     = ze0;  ys[ch0][te + 1]     = zo0;
        ys[ch0 + 1][te] = ze1;  ys[ch0 + 1][te + 1] = zo1;
    }
    __syncthreads();
    // LN stats: 64 channels per t
    {
        int grp = tid >> 6, tsel = tid & 63;      // 4 groups x 16 ch
        float s = 0.f, ss = 0.f;
#pragma unroll
        for (int q = 0; q < 16; q++) {
            float v = ys[grp*16 + q][tsel];
            s += v; ss += v*v;
        }
        rsum[grp][tsel] = s; rss2[grp][tsel] = ss;
    }
    __syncthreads();
    if (tid < 64) {
        float s = rsum[0][tid] + rsum[1][tid] + rsum[2][tid] + rsum[3][tid];
        float ss = rss2[0][tid] + rss2[1][tid] + rss2[2][tid] + rss2[3][tid];
        float m = s / 64.f;
        float var = ss / 64.f - m*m;
        mu[tid] = m; rstd[tid] = rsqrtf(var + EPSF);
    }
    __syncthreads();
    float lg0 = lg[lay*HH + ch0], lg1 = lg[lay*HH + ch0 + 1];
    float lb0 = lb[lay*HH + ch0], lb1 = lb[lay*HH + ch0 + 1];
    float* o0p = g_h + (b*HH + ch0)*T3 + t0;
    float* o1p = o0p + T3;
#pragma unroll
    for (int q = 0; q < 8; q++) {
        int tt = tsub + q;
        if (t0 + tt < T3) {
            float m = mu[tt], rr = rstd[tt];
            o0p[tt] = (z0[q] - m) * rr * lg0 + lb0;
            o1p[tt] = (z1[q] - m) * rr * lg1 + lb1;
        }
    }
}

// ---------------- decoder v2: 64o x 128t tiles, t-pair accumulation ----------------
__global__ __launch_bounds__(256) void k_dec(const float* __restrict__ dw,
                                             const float* __restrict__ db,
                                             float* __restrict__ out) {
    __shared__ float wsd[HH][64];
    __shared__ float hsd[HH][128];
    int o0b = blockIdx.x * 64, t0 = blockIdx.y * 128, b = blockIdx.z;
    int tid = threadIdx.x;
    for (int i = tid; i < HH*64; i += 256) {
        int d = i >> 6, o = i & 63;
        wsd[d][o] = dw[d*DOUT + o0b + o];
    }
    for (int i = tid; i < HH*128; i += 256) {
        int d = i >> 7, tt = i & 127;
        int t = t0 + tt;
        hsd[d][tt] = (t < T3) ? g_h[(b*HH + d)*T3 + t] : 0.f;
    }
    __syncthreads();
    int ogrp = tid & 15, tgrp = tid >> 4;       // 16 o-groups x 16 t-groups
    int o0 = ogrp * 4, tsub = tgrp * 8;
    ull acc[4][4];                              // [o][t-pair]
    {
#pragma unroll
        for (int o = 0; o < 4; o++) {
            float bo = db[o0b + o0 + o];
            ull iv = pk2(bo, bo);
#pragma unroll
            for (int t = 0; t < 4; t++) acc[o][t] = iv;
        }
    }
#pragma unroll 4
    for (int k = 0; k < HH; k++) {
        ull wp0 = *(const ull*)&wsd[k][o0];
        ull wp1 = *(const ull*)&wsd[k][o0 + 2];
        float w0, w1, w2, w3;
        upk2(wp0, w0, w1); upk2(wp1, w2, w3);
        ull W0 = pk2(w0, w0), W1 = pk2(w1, w1), W2 = pk2(w2, w2), W3 = pk2(w3, w3);
        ulonglong2 hA = *(const ulonglong2*)&hsd[k][tsub];
        ulonglong2 hB = *(const ulonglong2*)&hsd[k][tsub + 4];
        acc[0][0] = ffma2(W0, hA.x, acc[0][0]);  acc[1][0] = ffma2(W1, hA.x, acc[1][0]);
        acc[2][0] = ffma2(W2, hA.x, acc[2][0]);  acc[3][0] = ffma2(W3, hA.x, acc[3][0]);
        acc[0][1] = ffma2(W0, hA.y, acc[0][1]);  acc[1][1] = ffma2(W1, hA.y, acc[1][1]);
        acc[2][1] = ffma2(W2, hA.y, acc[2][1]);  acc[3][1] = ffma2(W3, hA.y, acc[3][1]);
        acc[0][2] = ffma2(W0, hB.x, acc[0][2]);  acc[1][2] = ffma2(W1, hB.x, acc[1][2]);
        acc[2][2] = ffma2(W2, hB.x, acc[2][2]);  acc[3][2] = ffma2(W3, hB.x, acc[3][2]);
        acc[0][3] = ffma2(W0, hB.y, acc[0][3]);  acc[1][3] = ffma2(W1, hB.y, acc[1][3]);
        acc[2][3] = ffma2(W2, hB.y, acc[2][3]);  acc[3][3] = ffma2(W3, hB.y, acc[3][3]);
    }
#pragma unroll
    for (int tp = 0; tp < 4; tp++) {
        int te = t0 + tsub + 2*tp;
        float a0e, a0o, a1e, a1o, a2e, a2o, a3e, a3o;
        upk2(acc[0][tp], a0e, a0o); upk2(acc[1][tp], a1e, a1o);
        upk2(acc[2][tp], a2e, a2o); upk2(acc[3][tp], a3e, a3o);
        if (te < T3) {
            float4 v = {a0e, a1e, a2e, a3e};
            *(float4*)&out[((size_t)(b*T3 + te))*DOUT + o0b + o0] = v;
        }
        if (te + 1 < T3) {
            float4 v = {a0o, a1o, a2o, a3o};
            *(float4*)&out[((size_t)(b*T3 + te + 1))*DOUT + o0b + o0] = v;
        }
    }
}

// ---------------- launcher ----------------
extern "C" void kernel_launch(void* const* d_in, const int* in_sizes, int n_in,
                              void* d_out, int out_size) {
    const float* x      = (const float*)d_in[0];
    const float* pw1w   = (const float*)d_in[1];
    const float* pw1b   = (const float*)d_in[2];
    const float* gn1g   = (const float*)d_in[3];
    const float* gn1b   = (const float*)d_in[4];
    const float* dww    = (const float*)d_in[5];
    const float* dwb    = (const float*)d_in[6];
    const float* gn2g   = (const float*)d_in[7];
    const float* gn2b   = (const float*)d_in[8];
    const float* pw2w   = (const float*)d_in[9];
    const float* pw2b   = (const float*)d_in[10];
    const float* encw   = (const float*)d_in[11];
    const float* encb   = (const float*)d_in[12];
    const float* logdt  = (const float*)d_in[13];
    const float* logA   = (const float*)d_in[14];
    const float* Aim    = (const float*)d_in[15];
    const float* Cre    = (const float*)d_in[16];
    const float* Cim    = (const float*)d_in[17];
    const float* s4D    = (const float*)d_in[18];
    const float* s4ow   = (const float*)d_in[19];
    const float* s4ob   = (const float*)d_in[20];
    const float* lng    = (const float*)d_in[21];
    const float* lnb    = (const float*)d_in[22];
    const float* decw   = (const float*)d_in[23];
    const float* decb   = (const float*)d_in[24];
    float* out = (float*)d_out;

    k_s4c<<<dim3(HH, NL), 64>>>(logdt, logA, Aim, Cre, Cim);
    k_pw1<<<dim3(T1/128, BB), 256>>>(x, pw1w, pw1b);
    k_dwf<<<dim3(2, CO, BB), 256>>>(dww, dwb, gn1g, gn1b);
    k_prep<<<9, 256>>>(pw2w, pw2b, encw, encb);
    k_enc<<<dim3(16, BB), 256>>>(gn2g, gn2b);
    for (int l = 0; l < NL; l++) {
        k_sc<<<(BB*HH*NSEG)/4, 128>>>(s4D, l);
        k_mix<<<dim3(32, BB), 256>>>(s4ow, s4ob, lng, lnb, l);
    }
    k_dec<<<dim3(DOUT/64, 16, BB), 256>>>(decw, decb, out);
}